// round 11
// baseline (speedup 1.0000x reference)
#include <cuda_runtime.h>
#include <cuda_bf16.h>
#include <math.h>
#include <stdint.h>

// Problem constants
#define NB    4
#define TSEQ  1024
#define CDIM  1024
#define NH    16
#define DH    64
#define MROWS (NB * TSEQ)      // 4096
#define KDIM  1024

// Scratch (device globals -- no allocation allowed)
__device__ __nv_bfloat16 g_Xhi[(size_t)MROWS * KDIM];
__device__ __nv_bfloat16 g_Xlo[(size_t)MROWS * KDIM];
__device__ __nv_bfloat16 g_Yhi[(size_t)MROWS * KDIM];
__device__ __nv_bfloat16 g_Ylo[(size_t)MROWS * KDIM];
__device__ __nv_bfloat16 g_WAhi[(size_t)3 * CDIM * KDIM];   // w_attn^T [n][k]
__device__ __nv_bfloat16 g_WAlo[(size_t)3 * CDIM * KDIM];
__device__ __nv_bfloat16 g_WPhi[(size_t)CDIM * KDIM];       // w_proj^T [n][k]
__device__ __nv_bfloat16 g_WPlo[(size_t)CDIM * KDIM];
__device__ __nv_bfloat16 g_Qh[(size_t)NB * NH * TSEQ * DH];
__device__ __nv_bfloat16 g_Qlo[(size_t)NB * NH * TSEQ * DH];
__device__ __nv_bfloat16 g_Kh[(size_t)NB * NH * TSEQ * DH];
__device__ __nv_bfloat16 g_Klo[(size_t)NB * NH * TSEQ * DH];
__device__ __nv_bfloat16 g_Vh[(size_t)NB * NH * TSEQ * DH];   // [bh][t][d] (like K)
__device__ __nv_bfloat16 g_Vlo[(size_t)NB * NH * TSEQ * DH];

// ---------------------------------------------------------------------------
// Helpers
// ---------------------------------------------------------------------------
__device__ __forceinline__ uint32_t smem_u32(const void* p) {
    return (uint32_t)__cvta_generic_to_shared(p);
}

__device__ __forceinline__ void cp_async16(uint32_t saddr, const void* gptr) {
    asm volatile("cp.async.cg.shared.global [%0], [%1], 16;" :: "r"(saddr), "l"(gptr));
}
#define CP_COMMIT() asm volatile("cp.async.commit_group;" ::: "memory")

__device__ __forceinline__ void ldsm_x4(uint32_t* r, uint32_t addr) {
    asm volatile("ldmatrix.sync.aligned.m8n8.x4.shared.b16 {%0,%1,%2,%3}, [%4];"
                 : "=r"(r[0]), "=r"(r[1]), "=r"(r[2]), "=r"(r[3]) : "r"(addr));
}

__device__ __forceinline__ void ldsm_x4_trans(uint32_t* r, uint32_t addr) {
    asm volatile("ldmatrix.sync.aligned.m8n8.x4.trans.shared.b16 {%0,%1,%2,%3}, [%4];"
                 : "=r"(r[0]), "=r"(r[1]), "=r"(r[2]), "=r"(r[3]) : "r"(addr));
}

__device__ __forceinline__ void mma_bf16(float* c, const uint32_t* a,
                                         uint32_t b0, uint32_t b1) {
    asm volatile(
        "mma.sync.aligned.m16n8k16.row.col.f32.bf16.bf16.f32 "
        "{%0,%1,%2,%3}, {%4,%5,%6,%7}, {%8,%9}, {%0,%1,%2,%3};"
        : "+f"(c[0]), "+f"(c[1]), "+f"(c[2]), "+f"(c[3])
        : "r"(a[0]), "r"(a[1]), "r"(a[2]), "r"(a[3]), "r"(b0), "r"(b1));
}

__device__ __forceinline__ void bsplit(float f, __nv_bfloat16& h, __nv_bfloat16& l) {
    h = __float2bfloat16_rn(f);
    l = __float2bfloat16_rn(f - __bfloat162float(h));
}

__device__ __forceinline__ float fast_exp2(float x) {
    float r;
    asm("ex2.approx.ftz.f32 %0, %1;" : "=f"(r) : "f"(x));
    return r;
}

// ---------------------------------------------------------------------------
// Fused preprocessing: transpose+split w_attn, w_proj; split x.
// Block (32,8). Grid: [0,3072) wA, [3072,4096) wP, [4096,8192) x split.
// ---------------------------------------------------------------------------
__device__ __forceinline__ void do_transpose_split(const float* __restrict__ src,
        __nv_bfloat16* dh, __nv_bfloat16* dl, int cols, int bx, int by,
        int tx, int ty, float tile[32][33])
{
    const int c0 = bx * 32;
    const int r0 = by * 32;
#pragma unroll
    for (int j = 0; j < 32; j += 8)
        tile[ty + j][tx] = src[(size_t)(r0 + ty + j) * cols + c0 + tx];
    __syncthreads();
#pragma unroll
    for (int j = 0; j < 32; j += 8) {
        float f = tile[tx][ty + j];
        __nv_bfloat16 h, l;
        bsplit(f, h, l);
        size_t o = (size_t)(c0 + ty + j) * KDIM + r0 + tx;
        dh[o] = h;
        dl[o] = l;
    }
}

__global__ __launch_bounds__(256) void preproc_kernel(const float* __restrict__ x,
        const float* __restrict__ wa, const float* __restrict__ wp)
{
    __shared__ float tile[32][33];
    const int bid = blockIdx.x;
    const int tx = threadIdx.x, ty = threadIdx.y;
    if (bid < 3072) {
        do_transpose_split(wa, g_WAhi, g_WAlo, 3 * CDIM, bid % 96, bid / 96, tx, ty, tile);
    } else if (bid < 4096) {
        const int r = bid - 3072;
        do_transpose_split(wp, g_WPhi, g_WPlo, CDIM, r % 32, r / 32, tx, ty, tile);
    } else {
        const int r = bid - 4096;
        const int tid = ty * 32 + tx;
        size_t i = ((size_t)r * 256 + tid) * 4;
        float4 v = *(const float4*)(x + i);
        __nv_bfloat16 h0, l0, h1, l1, h2, l2, h3, l3;
        bsplit(v.x, h0, l0); bsplit(v.y, h1, l1);
        bsplit(v.z, h2, l2); bsplit(v.w, h3, l3);
        __nv_bfloat162* ph = (__nv_bfloat162*)(g_Xhi + i);
        __nv_bfloat162* pl = (__nv_bfloat162*)(g_Xlo + i);
        __nv_bfloat162 a; a.x = h0; a.y = h1;
        __nv_bfloat162 b; b.x = h2; b.y = h3;
        ph[0] = a; ph[1] = b;
        a.x = l0; a.y = l1; b.x = l2; b.y = l3;
        pl[0] = a; pl[1] = b;
    }
}

// ---------------------------------------------------------------------------
// 3xBF16 mma.sync GEMM. BK=32, 3 stages, 2 CTAs/SM.
// Mainloop reordered: next-tile cp.async issued BEFORE compute; B-fragment
// ldsm interleaved with first half of MMAs.
// MODE0: QKV -> pre-split bf16 Q/K/V, stored [bh][t][d].
// MODE1: proj -> out fp32 [m][n]
// ---------------------------------------------------------------------------
#define GBM 128
#define GBN 128
#define GBK 32
#define KTILES  (KDIM / GBK)            // 32
#define PANEL   8192                     // 128 rows x 64 B
#define STAGE   (4 * PANEL)              // AH, AL, BH, BL = 32768
#define GSMEM   (3 * STAGE)              // 98304
#define OAH 0
#define OAL 8192
#define OBH 16384
#define OBL 24576

__device__ __forceinline__ uint32_t sw64(int row, int ch) {
    return (uint32_t)row * 64 + (uint32_t)((ch ^ ((row >> 1) & 3)) << 4);
}

__device__ __forceinline__ void load_tile_b(uint32_t sg,
        const __nv_bfloat16* Ah, const __nv_bfloat16* Al,
        const __nv_bfloat16* Bh, const __nv_bfloat16* Bl,
        int k0, int tid)
{
#pragma unroll
    for (int l = 0; l < 8; l++) {
        int idx = tid + l * 256;          // 0..2047
        int panel = idx >> 9;             // 0..3
        int rem = idx & 511;
        int row = rem >> 2;               // 0..127
        int ch  = rem & 3;                // 16B chunk along k (8 bf16)
        uint32_t sw = sw64(row, ch);
        const size_t g = (size_t)row * KDIM + k0 + ch * 8;
        const __nv_bfloat16* src = (panel == 0) ? Ah : (panel == 1) ? Al
                                  : (panel == 2) ? Bh : Bl;
        cp_async16(sg + (uint32_t)panel * PANEL + sw, src + g);
    }
}

template <int N, int MODE>
__global__ __launch_bounds__(256, 2) void tc_gemm(const float* __restrict__ bias,
                                                  float* __restrict__ out)
{
    extern __shared__ char smem[];
    const uint32_t sbase = smem_u32(smem);
    const int tid  = threadIdx.x;
    const int warp = tid >> 5;
    const int lane = tid & 31;
    const int wm = warp >> 1;             // 0..3
    const int wn = warp & 1;              // 0..1
    const int bm = blockIdx.y * GBM;
    const int bn = blockIdx.x * GBN;

    const __nv_bfloat16* Ah = ((MODE == 0) ? g_Xhi : g_Yhi) + (size_t)bm * KDIM;
    const __nv_bfloat16* Al = ((MODE == 0) ? g_Xlo : g_Ylo) + (size_t)bm * KDIM;
    const __nv_bfloat16* Bh = ((MODE == 0) ? g_WAhi : g_WPhi) + (size_t)bn * KDIM;
    const __nv_bfloat16* Bl = ((MODE == 0) ? g_WAlo : g_WPlo) + (size_t)bn * KDIM;

    const int arow = wm * 32 + (lane & 15);
    const int acb = (lane >> 4) & 1;
    const int brow = wn * 64 + (lane & 7) + ((lane & 16) >> 1);
    const int bcb = (lane >> 3) & 1;

    float acc[2][8][4];
#pragma unroll
    for (int mi = 0; mi < 2; mi++)
#pragma unroll
        for (int ni = 0; ni < 8; ni++)
#pragma unroll
            for (int r = 0; r < 4; r++) acc[mi][ni][r] = 0.0f;

#pragma unroll
    for (int t = 0; t < 2; t++) {
        load_tile_b(sbase + t * STAGE, Ah, Al, Bh, Bl, t * GBK, tid);
        CP_COMMIT();
    }

    for (int t = 0; t < KTILES; t++) {
        if (t < KTILES - 2)
            asm volatile("cp.async.wait_group 1;" ::: "memory");
        else
            asm volatile("cp.async.wait_group 0;" ::: "memory");
        __syncthreads();

        // Issue next-tile loads FIRST: buffer (t+2)%3 == (t-1)%3 is free
        // (all warps passed the sync, so tile t-1 compute is done).
        if (t + 2 < KTILES) {
            load_tile_b(sbase + (uint32_t)((t + 2) % 3) * STAGE,
                        Ah, Al, Bh, Bl, (t + 2) * GBK, tid);
            CP_COMMIT();
        }

        const uint32_t sg = sbase + (uint32_t)(t % 3) * STAGE;

#pragma unroll
        for (int ks = 0; ks < 2; ks++) {
            uint32_t ah[2][4], al[2][4], bh[4][4], bl[4][4];
#pragma unroll
            for (int mi = 0; mi < 2; mi++) {
                uint32_t ao = sw64(arow + mi * 16, ks * 2 + acb);
                ldsm_x4(ah[mi], sg + OAH + ao);
                ldsm_x4(al[mi], sg + OAL + ao);
            }
            // First half of B fragments
#pragma unroll
            for (int pi = 0; pi < 2; pi++) {
                uint32_t bo = sw64(brow + pi * 16, ks * 2 + bcb);
                ldsm_x4(bh[pi], sg + OBH + bo);
                ldsm_x4(bl[pi], sg + OBL + bo);
            }
            // MMAs for ni 0..3 (consume B pi 0..1)
#pragma unroll
            for (int mi = 0; mi < 2; mi++)
#pragma unroll
                for (int ni = 0; ni < 4; ni++) {
                    const int pi = ni >> 1;
                    const int j0 = (ni & 1) * 2;
                    mma_bf16(acc[mi][ni], al[mi], bh[pi][j0], bh[pi][j0 + 1]);
                    mma_bf16(acc[mi][ni], ah[mi], bl[pi][j0], bl[pi][j0 + 1]);
                    mma_bf16(acc[mi][ni], ah[mi], bh[pi][j0], bh[pi][j0 + 1]);
                }
            // Second half of B fragments
#pragma unroll
            for (int pi = 2; pi < 4; pi++) {
                uint32_t bo = sw64(brow + pi * 16, ks * 2 + bcb);
                ldsm_x4(bh[pi], sg + OBH + bo);
                ldsm_x4(bl[pi], sg + OBL + bo);
            }
            // MMAs for ni 4..7 (consume B pi 2..3)
#pragma unroll
            for (int mi = 0; mi < 2; mi++)
#pragma unroll
                for (int ni = 4; ni < 8; ni++) {
                    const int pi = ni >> 1;
                    const int j0 = (ni & 1) * 2;
                    mma_bf16(acc[mi][ni], al[mi], bh[pi][j0], bh[pi][j0 + 1]);
                    mma_bf16(acc[mi][ni], ah[mi], bl[pi][j0], bl[pi][j0 + 1]);
                    mma_bf16(acc[mi][ni], ah[mi], bh[pi][j0], bh[pi][j0 + 1]);
                }
        }
    }

    // Epilogue
#pragma unroll
    for (int mi = 0; mi < 2; mi++) {
#pragma unroll
        for (int ni = 0; ni < 8; ni++) {
            const int col = bn + wn * 64 + ni * 8 + (lane & 3) * 2;
            float2 bv = *(const float2*)(bias + col);
#pragma unroll
            for (int half = 0; half < 2; half++) {
                const int row = bm + wm * 32 + mi * 16 + (lane >> 2) + half * 8;
                float vx = acc[mi][ni][half * 2 + 0] + bv.x;
                float vy = acc[mi][ni][half * 2 + 1] + bv.y;
                if (MODE == 0) {
                    const int sec  = col >> 10;          // 0=q, 1=k, 2=v
                    const int cc   = col & 1023;
                    const int head = cc >> 6;
                    const int dpos = cc & 63;
                    const int b  = row >> 10;
                    const int tt = row & 1023;
                    const int bh2 = b * NH + head;
                    __nv_bfloat16 hx, lx, hy, ly;
                    bsplit(vx, hx, lx); bsplit(vy, hy, ly);
                    __nv_bfloat16* dh = (sec == 0) ? g_Qh : (sec == 1) ? g_Kh : g_Vh;
                    __nv_bfloat16* dl = (sec == 0) ? g_Qlo : (sec == 1) ? g_Klo : g_Vlo;
                    size_t o = ((size_t)bh2 * TSEQ + tt) * DH + dpos;
                    __nv_bfloat162 hv; hv.x = hx; hv.y = hy;
                    __nv_bfloat162 lv; lv.x = lx; lv.y = ly;
                    *(__nv_bfloat162*)(dh + o) = hv;
                    *(__nv_bfloat162*)(dl + o) = lv;
                } else {
                    float2 v2; v2.x = vx; v2.y = vy;
                    *(float2*)(out + (size_t)row * N + col) = v2;
                }
            }
        }
    }
}

// ---------------------------------------------------------------------------
// Tensor-core flash attention, 3xBF16, register-resident P, double-buffered
// K/V, trans-ldmatrix V. (unchanged from R10)
// ---------------------------------------------------------------------------
#define ABQ   128
#define ABK   64
#define SQH 0
#define SQL 16384
#define SKV 32768          // stage s at SKV + s*32768: {KH 0, KL 8K, VH 16K, VL 24K}
#define ASMEM 98304

__device__ __forceinline__ void attn_load_kv(uint32_t sbuf,
        const __nv_bfloat16* Khp, const __nv_bfloat16* Klp,
        const __nv_bfloat16* Vhp, const __nv_bfloat16* Vlp,
        int k0, int tid)
{
#pragma unroll
    for (int l = 0; l < 4; l++) {
        int idx = tid + l * 256;
        int panel = idx >> 9;            // 0 = hi, 1 = lo
        int rem = idx & 511;
        int r = rem >> 3, ch = rem & 7;
        uint32_t off = (uint32_t)r * 128 + ch * 16;
        uint32_t sw = off ^ ((off >> 3) & 0x70);
        cp_async16(sbuf + (panel ? 8192 : 0) + sw,
                   (panel ? Klp : Khp) + (size_t)(k0 + r) * DH + ch * 8);
        cp_async16(sbuf + (panel ? 24576 : 16384) + sw,
                   (panel ? Vlp : Vhp) + (size_t)(k0 + r) * DH + ch * 8);
    }
}

__global__ __launch_bounds__(256, 2) void attn_kernel()
{
    extern __shared__ char smc[];
    const uint32_t sb = smem_u32(smc);

    const int qi = gridDim.x - 1 - blockIdx.x;   // heavy tiles first
    const int bh = blockIdx.y;
    const int bb = bh >> 4, hh = bh & 15;
    const __nv_bfloat16* Qhp = g_Qh  + (size_t)bh * TSEQ * DH;
    const __nv_bfloat16* Qlp = g_Qlo + (size_t)bh * TSEQ * DH;
    const __nv_bfloat16* Khp = g_Kh  + (size_t)bh * TSEQ * DH;
    const __nv_bfloat16* Klp = g_Klo + (size_t)bh * TSEQ * DH;
    const __nv_bfloat16* Vhp = g_Vh  + (size_t)bh * TSEQ * DH;
    const __nv_bfloat16* Vlp = g_Vlo + (size_t)bh * TSEQ * DH;

    const int tid  = threadIdx.x;
    const int warp = tid >> 5;
    const int lane = tid & 31;
    const int rA   = lane >> 2;
    const int qcol = (lane & 3) * 2;

    const int acb  = (lane >> 4) & 1;
    const int bcb  = (lane >> 3) & 1;
    const int brow = (lane & 7) + ((lane & 16) >> 1);
    const int koff = (((lane >> 3) & 1) << 3) + (lane & 7);
    const int noct = lane >> 4;

    // Q panels (hi+lo): committed together with K/V tile 0
#pragma unroll
    for (int l = 0; l < 8; l++) {
        int idx = tid + l * 256;
        int panel = idx >> 10;
        int rem = idx & 1023;
        int r = rem >> 3, ch = rem & 7;
        uint32_t off = (uint32_t)r * 128 + ch * 16;
        uint32_t sw = off ^ ((off >> 3) & 0x70);
        const __nv_bfloat16* src = (panel ? Qlp : Qhp) + (size_t)(qi * ABQ + r) * DH + ch * 8;
        cp_async16(sb + (panel ? SQL : SQH) + sw, src);
    }
    attn_load_kv(sb + SKV, Khp, Klp, Vhp, Vlp, 0, tid);
    CP_COMMIT();

    float o[8][4];
#pragma unroll
    for (int ni = 0; ni < 8; ni++)
#pragma unroll
        for (int j = 0; j < 4; j++) o[ni][j] = 0.0f;
    float mA = -1e30f, mB = -1e30f, lAcc = 0.0f, lBcc = 0.0f;

    const float CS = 0.18033688011112042f;   // 0.125 * log2(e)
    const int ntiles = 2 * qi + 2;

    for (int kt = 0; kt < ntiles; kt++) {
        if (kt + 1 < ntiles) {
            attn_load_kv(sb + SKV + ((kt + 1) & 1) * 32768,
                         Khp, Klp, Vhp, Vlp, (kt + 1) * ABK, tid);
            CP_COMMIT();
            asm volatile("cp.async.wait_group 1;" ::: "memory");
        } else {
            asm volatile("cp.async.wait_group 0;" ::: "memory");
        }
        __syncthreads();

        const uint32_t skv = sb + SKV + (uint32_t)(kt & 1) * 32768;

        if (kt * ABK <= qi * ABQ + warp * 16 + 15) {
            // ---- S = Q K^T (3xbf16) ----
            float s[8][4];
#pragma unroll
            for (int ni = 0; ni < 8; ni++)
#pragma unroll
                for (int j = 0; j < 4; j++) s[ni][j] = 0.0f;

            const int aQrow = warp * 16 + (lane & 15);
            const uint32_t a_ro = (uint32_t)aQrow * 128;
            const int a_rx = aQrow & 7;
#pragma unroll
            for (int ks = 0; ks < 4; ks++) {
                uint32_t ah[4], al[4], kh[4][4], kl[4][4];
                uint32_t ao = a_ro + (uint32_t)(((ks * 2 + acb) ^ a_rx) << 4);
                ldsm_x4(ah, sb + SQH + ao);
                ldsm_x4(al, sb + SQL + ao);
#pragma unroll
                for (int pi = 0; pi < 4; pi++) {
                    int br = pi * 16 + brow;
                    uint32_t bo = (uint32_t)br * 128 +
                                  (uint32_t)(((ks * 2 + bcb) ^ (br & 7)) << 4);
                    ldsm_x4(kh[pi], skv + bo);           // K hi
                    ldsm_x4(kl[pi], skv + 8192 + bo);    // K lo
                }
#pragma unroll
                for (int ni = 0; ni < 8; ni++) {
                    const int pi = ni >> 1, j0 = (ni & 1) * 2;
                    mma_bf16(s[ni], al, kh[pi][j0], kh[pi][j0 + 1]);
                    mma_bf16(s[ni], ah, kl[pi][j0], kl[pi][j0 + 1]);
                    mma_bf16(s[ni], ah, kh[pi][j0], kh[pi][j0 + 1]);
                }
            }

            // ---- scale + causal mask ----
            const bool needmask = (kt * ABK + ABK - 1 > qi * ABQ + warp * 16);
            const int rowgA = qi * ABQ + warp * 16 + rA;
            const int rowgB = rowgA + 8;
            const int cb = kt * ABK + qcol;
#pragma unroll
            for (int ni = 0; ni < 8; ni++) {
                float z0 = s[ni][0] * CS, z1 = s[ni][1] * CS;
                float z2 = s[ni][2] * CS, z3 = s[ni][3] * CS;
                if (needmask) {
                    int c0 = cb + ni * 8, c1 = c0 + 1;
                    if (c0 > rowgA) z0 = -1e30f;
                    if (c1 > rowgA) z1 = -1e30f;
                    if (c0 > rowgB) z2 = -1e30f;
                    if (c1 > rowgB) z3 = -1e30f;
                }
                s[ni][0] = z0; s[ni][1] = z1; s[ni][2] = z2; s[ni][3] = z3;
            }

            // ---- online softmax ----
            float mtA = -1e30f, mtB = -1e30f;
#pragma unroll
            for (int ni = 0; ni < 8; ni++) {
                mtA = fmaxf(mtA, fmaxf(s[ni][0], s[ni][1]));
                mtB = fmaxf(mtB, fmaxf(s[ni][2], s[ni][3]));
            }
            mtA = fmaxf(mtA, __shfl_xor_sync(0xffffffffu, mtA, 1));
            mtA = fmaxf(mtA, __shfl_xor_sync(0xffffffffu, mtA, 2));
            mtB = fmaxf(mtB, __shfl_xor_sync(0xffffffffu, mtB, 1));
            mtB = fmaxf(mtB, __shfl_xor_sync(0xffffffffu, mtB, 2));

            const float mnA = fmaxf(mA, mtA);
            const float mnB = fmaxf(mB, mtB);
            const float aAl = fast_exp2(mA - mnA);
            const float aBl = fast_exp2(mB - mnB);
            mA = mnA; mB = mnB;

            float psA = 0.0f, psB = 0.0f;
#pragma unroll
            for (int ni = 0; ni < 8; ni++) {
                float p0 = fast_exp2(s[ni][0] - mnA);
                float p1 = fast_exp2(s[ni][1] - mnA);
                float p2 = fast_exp2(s[ni][2] - mnB);
                float p3 = fast_exp2(s[ni][3] - mnB);
                psA += p0 + p1; psB += p2 + p3;
                s[ni][0] = p0; s[ni][1] = p1; s[ni][2] = p2; s[ni][3] = p3;
            }
            psA += __shfl_xor_sync(0xffffffffu, psA, 1);
            psA += __shfl_xor_sync(0xffffffffu, psA, 2);
            psB += __shfl_xor_sync(0xffffffffu, psB, 1);
            psB += __shfl_xor_sync(0xffffffffu, psB, 2);
            lAcc = lAcc * aAl + psA;
            lBcc = lBcc * aBl + psB;

#pragma unroll
            for (int ni = 0; ni < 8; ni++) {
                o[ni][0] *= aAl; o[ni][1] *= aAl;
                o[ni][2] *= aBl; o[ni][3] *= aBl;
            }

            // ---- O += P V (3xbf16), P in registers, V via ldsm.trans ----
#pragma unroll
            for (int j = 0; j < 4; j++) {   // k-step over 16 keys
                uint32_t pa_h[4], pa_l[4];
#pragma unroll
                for (int half = 0; half < 2; half++) {   // kblk 0 / 8
                    const float* sp = s[2 * j + half];
                    __nv_bfloat162 h0 = __floats2bfloat162_rn(sp[0], sp[1]);
                    __nv_bfloat162 h1 = __floats2bfloat162_rn(sp[2], sp[3]);
                    __nv_bfloat162 l0 = __floats2bfloat162_rn(
                        sp[0] - __bfloat162float(h0.x), sp[1] - __bfloat162float(h0.y));
                    __nv_bfloat162 l1 = __floats2bfloat162_rn(
                        sp[2] - __bfloat162float(h1.x), sp[3] - __bfloat162float(h1.y));
                    pa_h[half * 2 + 0] = *(uint32_t*)&h0;
                    pa_h[half * 2 + 1] = *(uint32_t*)&h1;
                    pa_l[half * 2 + 0] = *(uint32_t*)&l0;
                    pa_l[half * 2 + 1] = *(uint32_t*)&l1;
                }

                uint32_t vh[4][4], vl[4][4];
                const int vrow = j * 16 + koff;          // key row in V panel
                const uint32_t vro = (uint32_t)vrow * 128;
                const int v_rx = vrow & 7;
#pragma unroll
                for (int pi = 0; pi < 4; pi++) {
                    uint32_t chv = (uint32_t)(2 * pi + noct);
                    uint32_t bo = vro + ((chv ^ (uint32_t)v_rx) << 4);
                    ldsm_x4_trans(vh[pi], skv + 16384 + bo);   // V hi
                    ldsm_x4_trans(vl[pi], skv + 24576 + bo);   // V lo
                }
#pragma unroll
                for (int ni = 0; ni < 8; ni++) {
                    const int pi = ni >> 1, j0 = (ni & 1) * 2;
                    mma_bf16(o[ni], pa_l, vh[pi][j0], vh[pi][j0 + 1]);
                    mma_bf16(o[ni], pa_h, vl[pi][j0], vl[pi][j0 + 1]);
                    mma_bf16(o[ni], pa_h, vh[pi][j0], vh[pi][j0 + 1]);
                }
            }
        }
        __syncthreads();   // all warps done with buf[kt&1] before its reload
    }

    // ---- epilogue: normalize, split to bf16, write g_Yhi/lo [b][t][c] ----
    const float invA = 1.0f / lAcc;
    const float invB = 1.0f / lBcc;
    const int tA = qi * ABQ + warp * 16 + rA;
    const int tB = tA + 8;
    const size_t baseA = ((size_t)bb * TSEQ + tA) * CDIM + hh * DH;
    const size_t baseB = ((size_t)bb * TSEQ + tB) * CDIM + hh * DH;
#pragma unroll
    for (int ni = 0; ni < 8; ni++) {
        int col = ni * 8 + qcol;
        float yA0 = o[ni][0] * invA, yA1 = o[ni][1] * invA;
        float yB0 = o[ni][2] * invB, yB1 = o[ni][3] * invB;
        __nv_bfloat16 h0, l0, h1, l1;
        __nv_bfloat162 hv, lv;
        bsplit(yA0, h0, l0); bsplit(yA1, h1, l1);
        hv.x = h0; hv.y = h1; lv.x = l0; lv.y = l1;
        *(__nv_bfloat162*)(g_Yhi + baseA + col) = hv;
        *(__nv_bfloat162*)(g_Ylo + baseA + col) = lv;
        bsplit(yB0, h0, l0); bsplit(yB1, h1, l1);
        hv.x = h0; hv.y = h1; lv.x = l0; lv.y = l1;
        *(__nv_bfloat162*)(g_Yhi + baseB + col) = hv;
        *(__nv_bfloat162*)(g_Ylo + baseB + col) = lv;
    }
}

// ---------------------------------------------------------------------------
// Launch
// ---------------------------------------------------------------------------
extern "C" void kernel_launch(void* const* d_in, const int* in_sizes, int n_in,
                              void* d_out, int out_size)
{
    const float* x      = (const float*)d_in[0];
    const float* w_attn = (const float*)d_in[1];
    const float* b_attn = (const float*)d_in[2];
    const float* w_proj = (const float*)d_in[3];
    const float* b_proj = (const float*)d_in[4];
    float* out = (float*)d_out;

    // 0) Fused preprocessing
    {
        dim3 blk(32, 8);
        preproc_kernel<<<8192, blk>>>(x, w_attn, w_proj);
    }

    // 1) QKV GEMM (3xbf16) -> pre-split Q/K/V [bh][t][d]
    {
        cudaFuncSetAttribute(tc_gemm<3 * CDIM, 0>,
                             cudaFuncAttributeMaxDynamicSharedMemorySize, GSMEM);
        dim3 grid(3 * CDIM / GBN, MROWS / GBM);   // (24, 32)
        tc_gemm<3 * CDIM, 0><<<grid, 256, GSMEM>>>(b_attn, nullptr);
    }

    // 2) Tensor-core flash attention (3xbf16, trans-ldmatrix V)
    {
        cudaFuncSetAttribute(attn_kernel,
                             cudaFuncAttributeMaxDynamicSharedMemorySize, ASMEM);
        dim3 grid(TSEQ / ABQ, NB * NH);           // (8, 64)
        attn_kernel<<<grid, 256, ASMEM>>>();
    }

    // 3) Output projection (3xbf16)
    {
        cudaFuncSetAttribute(tc_gemm<CDIM, 1>,
                             cudaFuncAttributeMaxDynamicSharedMemorySize, GSMEM);
        dim3 grid(CDIM / GBN, MROWS / GBM);       // (8, 32)
        tc_gemm<CDIM, 1><<<grid, 256, GSMEM>>>(b_proj, out);
    }
}

// round 12
// speedup vs baseline: 1.0589x; 1.0589x over previous
#include <cuda_runtime.h>
#include <cuda_bf16.h>
#include <math.h>
#include <stdint.h>

// Problem constants
#define NB    4
#define TSEQ  1024
#define CDIM  1024
#define NH    16
#define DH    64
#define MROWS (NB * TSEQ)      // 4096
#define KDIM  1024

// Scratch (device globals -- no allocation allowed)
__device__ __nv_bfloat16 g_Xhi[(size_t)MROWS * KDIM];
__device__ __nv_bfloat16 g_Xlo[(size_t)MROWS * KDIM];
__device__ __nv_bfloat16 g_Yhi[(size_t)MROWS * KDIM];
__device__ __nv_bfloat16 g_Ylo[(size_t)MROWS * KDIM];
__device__ __nv_bfloat16 g_WAhi[(size_t)KDIM * 3 * CDIM];   // w_attn [k][n] (natural)
__device__ __nv_bfloat16 g_WAlo[(size_t)KDIM * 3 * CDIM];
__device__ __nv_bfloat16 g_WPhi[(size_t)KDIM * CDIM];       // w_proj [k][n] (natural)
__device__ __nv_bfloat16 g_WPlo[(size_t)KDIM * CDIM];
__device__ __nv_bfloat16 g_Qh[(size_t)NB * NH * TSEQ * DH];
__device__ __nv_bfloat16 g_Qlo[(size_t)NB * NH * TSEQ * DH];
__device__ __nv_bfloat16 g_Kh[(size_t)NB * NH * TSEQ * DH];
__device__ __nv_bfloat16 g_Klo[(size_t)NB * NH * TSEQ * DH];
__device__ __nv_bfloat16 g_Vh[(size_t)NB * NH * TSEQ * DH];   // [bh][t][d]
__device__ __nv_bfloat16 g_Vlo[(size_t)NB * NH * TSEQ * DH];

// ---------------------------------------------------------------------------
// Helpers
// ---------------------------------------------------------------------------
__device__ __forceinline__ uint32_t smem_u32(const void* p) {
    return (uint32_t)__cvta_generic_to_shared(p);
}

__device__ __forceinline__ void cp_async16(uint32_t saddr, const void* gptr) {
    asm volatile("cp.async.cg.shared.global [%0], [%1], 16;" :: "r"(saddr), "l"(gptr));
}
#define CP_COMMIT() asm volatile("cp.async.commit_group;" ::: "memory")

__device__ __forceinline__ void ldsm_x4(uint32_t* r, uint32_t addr) {
    asm volatile("ldmatrix.sync.aligned.m8n8.x4.shared.b16 {%0,%1,%2,%3}, [%4];"
                 : "=r"(r[0]), "=r"(r[1]), "=r"(r[2]), "=r"(r[3]) : "r"(addr));
}

__device__ __forceinline__ void ldsm_x4_trans(uint32_t* r, uint32_t addr) {
    asm volatile("ldmatrix.sync.aligned.m8n8.x4.trans.shared.b16 {%0,%1,%2,%3}, [%4];"
                 : "=r"(r[0]), "=r"(r[1]), "=r"(r[2]), "=r"(r[3]) : "r"(addr));
}

__device__ __forceinline__ void mma_bf16(float* c, const uint32_t* a,
                                         uint32_t b0, uint32_t b1) {
    asm volatile(
        "mma.sync.aligned.m16n8k16.row.col.f32.bf16.bf16.f32 "
        "{%0,%1,%2,%3}, {%4,%5,%6,%7}, {%8,%9}, {%0,%1,%2,%3};"
        : "+f"(c[0]), "+f"(c[1]), "+f"(c[2]), "+f"(c[3])
        : "r"(a[0]), "r"(a[1]), "r"(a[2]), "r"(a[3]), "r"(b0), "r"(b1));
}

__device__ __forceinline__ void bsplit(float f, __nv_bfloat16& h, __nv_bfloat16& l) {
    h = __float2bfloat16_rn(f);
    l = __float2bfloat16_rn(f - __bfloat162float(h));
}

__device__ __forceinline__ float fast_exp2(float x) {
    float r;
    asm("ex2.approx.ftz.f32 %0, %1;" : "=f"(r) : "f"(x));
    return r;
}

// ---------------------------------------------------------------------------
// Fused preprocessing: pure elementwise bf16 split (NO transposes).
// Grid blocks: [0,3072) w_attn; [3072,4096) w_proj; [4096,8192) x.
// Each block: 256 threads x 4 floats.
// ---------------------------------------------------------------------------
__device__ __forceinline__ void split4(const float* __restrict__ s,
        __nv_bfloat16* dh, __nv_bfloat16* dl, size_t i)
{
    float4 v = *(const float4*)(s + i);
    __nv_bfloat16 h0, l0, h1, l1, h2, l2, h3, l3;
    bsplit(v.x, h0, l0); bsplit(v.y, h1, l1);
    bsplit(v.z, h2, l2); bsplit(v.w, h3, l3);
    __nv_bfloat162* ph = (__nv_bfloat162*)(dh + i);
    __nv_bfloat162* pl = (__nv_bfloat162*)(dl + i);
    __nv_bfloat162 a; a.x = h0; a.y = h1;
    __nv_bfloat162 b; b.x = h2; b.y = h3;
    ph[0] = a; ph[1] = b;
    a.x = l0; a.y = l1; b.x = l2; b.y = l3;
    pl[0] = a; pl[1] = b;
}

__global__ __launch_bounds__(256) void preproc_kernel(const float* __restrict__ x,
        const float* __restrict__ wa, const float* __restrict__ wp)
{
    const int bid = blockIdx.x;
    const int tid = threadIdx.x;
    if (bid < 3072) {
        size_t i = ((size_t)bid * 256 + tid) * 4;
        split4(wa, g_WAhi, g_WAlo, i);
    } else if (bid < 4096) {
        size_t i = ((size_t)(bid - 3072) * 256 + tid) * 4;
        split4(wp, g_WPhi, g_WPlo, i);
    } else {
        size_t i = ((size_t)(bid - 4096) * 256 + tid) * 4;
        split4(x, g_Xhi, g_Xlo, i);
    }
}

// ---------------------------------------------------------------------------
// 3xBF16 mma.sync GEMM. A: [m][k] hi/lo; B: NATURAL [k][n] hi/lo, consumed
// via ldmatrix.trans. BK=32, 3 stages = 96KB -> 2 CTAs/SM.
// MODE0: QKV -> pre-split bf16 Q/K/V [bh][t][d]. MODE1: proj -> fp32 out.
// ---------------------------------------------------------------------------
#define GBM 128
#define GBN 128
#define GBK 32
#define KTILES  (KDIM / GBK)            // 32
#define PANEL   8192                     // A: 128r x 64B; B: 32r x 256B
#define STAGE   (4 * PANEL)              // AH, AL, BH, BL = 32768
#define GSMEM   (3 * STAGE)              // 98304
#define OAH 0
#define OAL 8192
#define OBH 16384
#define OBL 24576

__device__ __forceinline__ uint32_t sw64(int row, int ch) {
    return (uint32_t)row * 64 + (uint32_t)((ch ^ ((row >> 1) & 3)) << 4);
}
// B panel swizzle: 256B rows (16 chunks), chunk ^= row&15
__device__ __forceinline__ uint32_t swB(int row, int ch) {
    return (uint32_t)row * 256 + (uint32_t)((ch ^ (row & 15)) << 4);
}

template <int N>
__device__ __forceinline__ void load_tile_b(uint32_t sg,
        const __nv_bfloat16* Ah, const __nv_bfloat16* Al,
        const __nv_bfloat16* Bh, const __nv_bfloat16* Bl,
        int k0, int tid)
{
#pragma unroll
    for (int l = 0; l < 8; l++) {
        int idx = tid + l * 256;          // 0..2047
        if (idx < 1024) {
            // A: 128 rows x 4 chunks, hi (panel 0) / lo (panel 1)
            int panel = idx >> 9;
            int rem = idx & 511;
            int row = rem >> 2;
            int ch  = rem & 3;
            cp_async16(sg + (panel ? OAL : OAH) + sw64(row, ch),
                       (panel ? Al : Ah) + (size_t)row * KDIM + k0 + ch * 8);
        } else {
            // B: 32 k-rows x 16 chunks of 8 n-cols, hi / lo
            int panel = (idx - 1024) >> 9;
            int rem = idx & 511;
            int row = rem >> 4;            // 0..31 (k)
            int ch  = rem & 15;            // n chunk
            cp_async16(sg + (panel ? OBL : OBH) + swB(row, ch),
                       (panel ? Bl : Bh) + (size_t)(k0 + row) * N + ch * 8);
        }
    }
}

template <int N, int MODE>
__global__ __launch_bounds__(256, 2) void tc_gemm(const float* __restrict__ bias,
                                                  float* __restrict__ out)
{
    extern __shared__ char smem[];
    const uint32_t sbase = smem_u32(smem);
    const int tid  = threadIdx.x;
    const int warp = tid >> 5;
    const int lane = tid & 31;
    const int wm = warp >> 1;             // 0..3
    const int wn = warp & 1;              // 0..1
    const int bm = blockIdx.y * GBM;
    const int bn = blockIdx.x * GBN;

    const __nv_bfloat16* Ah = ((MODE == 0) ? g_Xhi : g_Yhi) + (size_t)bm * KDIM;
    const __nv_bfloat16* Al = ((MODE == 0) ? g_Xlo : g_Ylo) + (size_t)bm * KDIM;
    const __nv_bfloat16* Bh = ((MODE == 0) ? g_WAhi : g_WPhi) + bn;
    const __nv_bfloat16* Bl = ((MODE == 0) ? g_WAlo : g_WPlo) + bn;

    const int arow = wm * 32 + (lane & 15);
    const int acb = (lane >> 4) & 1;
    // trans-ldsm lane mapping (validated in attention V path)
    const int koffG = (((lane >> 3) & 1) << 3) + (lane & 7);
    const int noctG = lane >> 4;

    float acc[2][8][4];
#pragma unroll
    for (int mi = 0; mi < 2; mi++)
#pragma unroll
        for (int ni = 0; ni < 8; ni++)
#pragma unroll
            for (int r = 0; r < 4; r++) acc[mi][ni][r] = 0.0f;

#pragma unroll
    for (int t = 0; t < 2; t++) {
        load_tile_b<N>(sbase + t * STAGE, Ah, Al, Bh, Bl, t * GBK, tid);
        CP_COMMIT();
    }

    for (int t = 0; t < KTILES; t++) {
        if (t < KTILES - 2)
            asm volatile("cp.async.wait_group 1;" ::: "memory");
        else
            asm volatile("cp.async.wait_group 0;" ::: "memory");
        __syncthreads();

        const uint32_t sg = sbase + (uint32_t)(t % 3) * STAGE;

#pragma unroll
        for (int ks = 0; ks < 2; ks++) {
            uint32_t ah[2][4], al[2][4], bh[4][4], bl[4][4];
#pragma unroll
            for (int mi = 0; mi < 2; mi++) {
                uint32_t ao = sw64(arow + mi * 16, ks * 2 + acb);
                ldsm_x4(ah[mi], sg + OAH + ao);
                ldsm_x4(al[mi], sg + OAL + ao);
            }
#pragma unroll
            for (int pi = 0; pi < 4; pi++) {
                int vr = ks * 16 + koffG;                 // k row in B panel
                int chv = wn * 8 + 2 * pi + noctG;        // n chunk
                uint32_t bo = swB(vr, chv);
                ldsm_x4_trans(bh[pi], sg + OBH + bo);
                ldsm_x4_trans(bl[pi], sg + OBL + bo);
            }
#pragma unroll
            for (int mi = 0; mi < 2; mi++)
#pragma unroll
                for (int ni = 0; ni < 8; ni++) {
                    const int pi = ni >> 1;
                    const int j0 = (ni & 1) * 2;
                    mma_bf16(acc[mi][ni], al[mi], bh[pi][j0], bh[pi][j0 + 1]);
                    mma_bf16(acc[mi][ni], ah[mi], bl[pi][j0], bl[pi][j0 + 1]);
                    mma_bf16(acc[mi][ni], ah[mi], bh[pi][j0], bh[pi][j0 + 1]);
                }
        }

        if (t + 2 < KTILES) {
            load_tile_b<N>(sbase + (uint32_t)((t + 2) % 3) * STAGE,
                           Ah, Al, Bh, Bl, (t + 2) * GBK, tid);
            CP_COMMIT();
        }
    }

    // Epilogue
#pragma unroll
    for (int mi = 0; mi < 2; mi++) {
#pragma unroll
        for (int ni = 0; ni < 8; ni++) {
            const int col = bn + wn * 64 + ni * 8 + (lane & 3) * 2;
            float2 bv = *(const float2*)(bias + col);
#pragma unroll
            for (int half = 0; half < 2; half++) {
                const int row = bm + wm * 32 + mi * 16 + (lane >> 2) + half * 8;
                float vx = acc[mi][ni][half * 2 + 0] + bv.x;
                float vy = acc[mi][ni][half * 2 + 1] + bv.y;
                if (MODE == 0) {
                    const int sec  = col >> 10;          // 0=q, 1=k, 2=v
                    const int cc   = col & 1023;
                    const int head = cc >> 6;
                    const int dpos = cc & 63;
                    const int b  = row >> 10;
                    const int tt = row & 1023;
                    const int bh2 = b * NH + head;
                    __nv_bfloat16 hx, lx, hy, ly;
                    bsplit(vx, hx, lx); bsplit(vy, hy, ly);
                    __nv_bfloat16* dh = (sec == 0) ? g_Qh : (sec == 1) ? g_Kh : g_Vh;
                    __nv_bfloat16* dl = (sec == 0) ? g_Qlo : (sec == 1) ? g_Klo : g_Vlo;
                    size_t o = ((size_t)bh2 * TSEQ + tt) * DH + dpos;
                    __nv_bfloat162 hv; hv.x = hx; hv.y = hy;
                    __nv_bfloat162 lv; lv.x = lx; lv.y = ly;
                    *(__nv_bfloat162*)(dh + o) = hv;
                    *(__nv_bfloat162*)(dl + o) = lv;
                } else {
                    float2 v2; v2.x = vx; v2.y = vy;
                    *(float2*)(out + (size_t)row * N + col) = v2;
                }
            }
        }
    }
}

// ---------------------------------------------------------------------------
// Tensor-core flash attention, 3xBF16, register-resident P, double-buffered
// K/V, trans-ldmatrix V. (unchanged from R10)
// ---------------------------------------------------------------------------
#define ABQ   128
#define ABK   64
#define SQH 0
#define SQL 16384
#define SKV 32768          // stage s at SKV + s*32768: {KH 0, KL 8K, VH 16K, VL 24K}
#define ASMEM 98304

__device__ __forceinline__ void attn_load_kv(uint32_t sbuf,
        const __nv_bfloat16* Khp, const __nv_bfloat16* Klp,
        const __nv_bfloat16* Vhp, const __nv_bfloat16* Vlp,
        int k0, int tid)
{
#pragma unroll
    for (int l = 0; l < 4; l++) {
        int idx = tid + l * 256;
        int panel = idx >> 9;            // 0 = hi, 1 = lo
        int rem = idx & 511;
        int r = rem >> 3, ch = rem & 7;
        uint32_t off = (uint32_t)r * 128 + ch * 16;
        uint32_t sw = off ^ ((off >> 3) & 0x70);
        cp_async16(sbuf + (panel ? 8192 : 0) + sw,
                   (panel ? Klp : Khp) + (size_t)(k0 + r) * DH + ch * 8);
        cp_async16(sbuf + (panel ? 24576 : 16384) + sw,
                   (panel ? Vlp : Vhp) + (size_t)(k0 + r) * DH + ch * 8);
    }
}

__global__ __launch_bounds__(256, 2) void attn_kernel()
{
    extern __shared__ char smc[];
    const uint32_t sb = smem_u32(smc);

    const int qi = gridDim.x - 1 - blockIdx.x;   // heavy tiles first
    const int bh = blockIdx.y;
    const int bb = bh >> 4, hh = bh & 15;
    const __nv_bfloat16* Qhp = g_Qh  + (size_t)bh * TSEQ * DH;
    const __nv_bfloat16* Qlp = g_Qlo + (size_t)bh * TSEQ * DH;
    const __nv_bfloat16* Khp = g_Kh  + (size_t)bh * TSEQ * DH;
    const __nv_bfloat16* Klp = g_Klo + (size_t)bh * TSEQ * DH;
    const __nv_bfloat16* Vhp = g_Vh  + (size_t)bh * TSEQ * DH;
    const __nv_bfloat16* Vlp = g_Vlo + (size_t)bh * TSEQ * DH;

    const int tid  = threadIdx.x;
    const int warp = tid >> 5;
    const int lane = tid & 31;
    const int rA   = lane >> 2;
    const int qcol = (lane & 3) * 2;

    const int acb  = (lane >> 4) & 1;
    const int bcb  = (lane >> 3) & 1;
    const int brow = (lane & 7) + ((lane & 16) >> 1);
    const int koff = (((lane >> 3) & 1) << 3) + (lane & 7);
    const int noct = lane >> 4;

    // Q panels (hi+lo): committed together with K/V tile 0
#pragma unroll
    for (int l = 0; l < 8; l++) {
        int idx = tid + l * 256;
        int panel = idx >> 10;
        int rem = idx & 1023;
        int r = rem >> 3, ch = rem & 7;
        uint32_t off = (uint32_t)r * 128 + ch * 16;
        uint32_t sw = off ^ ((off >> 3) & 0x70);
        const __nv_bfloat16* src = (panel ? Qlp : Qhp) + (size_t)(qi * ABQ + r) * DH + ch * 8;
        cp_async16(sb + (panel ? SQL : SQH) + sw, src);
    }
    attn_load_kv(sb + SKV, Khp, Klp, Vhp, Vlp, 0, tid);
    CP_COMMIT();

    float o[8][4];
#pragma unroll
    for (int ni = 0; ni < 8; ni++)
#pragma unroll
        for (int j = 0; j < 4; j++) o[ni][j] = 0.0f;
    float mA = -1e30f, mB = -1e30f, lAcc = 0.0f, lBcc = 0.0f;

    const float CS = 0.18033688011112042f;   // 0.125 * log2(e)
    const int ntiles = 2 * qi + 2;

    for (int kt = 0; kt < ntiles; kt++) {
        if (kt + 1 < ntiles) {
            attn_load_kv(sb + SKV + ((kt + 1) & 1) * 32768,
                         Khp, Klp, Vhp, Vlp, (kt + 1) * ABK, tid);
            CP_COMMIT();
            asm volatile("cp.async.wait_group 1;" ::: "memory");
        } else {
            asm volatile("cp.async.wait_group 0;" ::: "memory");
        }
        __syncthreads();

        const uint32_t skv = sb + SKV + (uint32_t)(kt & 1) * 32768;

        if (kt * ABK <= qi * ABQ + warp * 16 + 15) {
            // ---- S = Q K^T (3xbf16) ----
            float s[8][4];
#pragma unroll
            for (int ni = 0; ni < 8; ni++)
#pragma unroll
                for (int j = 0; j < 4; j++) s[ni][j] = 0.0f;

            const int aQrow = warp * 16 + (lane & 15);
            const uint32_t a_ro = (uint32_t)aQrow * 128;
            const int a_rx = aQrow & 7;
#pragma unroll
            for (int ks = 0; ks < 4; ks++) {
                uint32_t ah[4], al[4], kh[4][4], kl[4][4];
                uint32_t ao = a_ro + (uint32_t)(((ks * 2 + acb) ^ a_rx) << 4);
                ldsm_x4(ah, sb + SQH + ao);
                ldsm_x4(al, sb + SQL + ao);
#pragma unroll
                for (int pi = 0; pi < 4; pi++) {
                    int br = pi * 16 + brow;
                    uint32_t bo = (uint32_t)br * 128 +
                                  (uint32_t)(((ks * 2 + bcb) ^ (br & 7)) << 4);
                    ldsm_x4(kh[pi], skv + bo);           // K hi
                    ldsm_x4(kl[pi], skv + 8192 + bo);    // K lo
                }
#pragma unroll
                for (int ni = 0; ni < 8; ni++) {
                    const int pi = ni >> 1, j0 = (ni & 1) * 2;
                    mma_bf16(s[ni], al, kh[pi][j0], kh[pi][j0 + 1]);
                    mma_bf16(s[ni], ah, kl[pi][j0], kl[pi][j0 + 1]);
                    mma_bf16(s[ni], ah, kh[pi][j0], kh[pi][j0 + 1]);
                }
            }

            // ---- scale + causal mask ----
            const bool needmask = (kt * ABK + ABK - 1 > qi * ABQ + warp * 16);
            const int rowgA = qi * ABQ + warp * 16 + rA;
            const int rowgB = rowgA + 8;
            const int cb = kt * ABK + qcol;
#pragma unroll
            for (int ni = 0; ni < 8; ni++) {
                float z0 = s[ni][0] * CS, z1 = s[ni][1] * CS;
                float z2 = s[ni][2] * CS, z3 = s[ni][3] * CS;
                if (needmask) {
                    int c0 = cb + ni * 8, c1 = c0 + 1;
                    if (c0 > rowgA) z0 = -1e30f;
                    if (c1 > rowgA) z1 = -1e30f;
                    if (c0 > rowgB) z2 = -1e30f;
                    if (c1 > rowgB) z3 = -1e30f;
                }
                s[ni][0] = z0; s[ni][1] = z1; s[ni][2] = z2; s[ni][3] = z3;
            }

            // ---- online softmax ----
            float mtA = -1e30f, mtB = -1e30f;
#pragma unroll
            for (int ni = 0; ni < 8; ni++) {
                mtA = fmaxf(mtA, fmaxf(s[ni][0], s[ni][1]));
                mtB = fmaxf(mtB, fmaxf(s[ni][2], s[ni][3]));
            }
            mtA = fmaxf(mtA, __shfl_xor_sync(0xffffffffu, mtA, 1));
            mtA = fmaxf(mtA, __shfl_xor_sync(0xffffffffu, mtA, 2));
            mtB = fmaxf(mtB, __shfl_xor_sync(0xffffffffu, mtB, 1));
            mtB = fmaxf(mtB, __shfl_xor_sync(0xffffffffu, mtB, 2));

            const float mnA = fmaxf(mA, mtA);
            const float mnB = fmaxf(mB, mtB);
            const float aAl = fast_exp2(mA - mnA);
            const float aBl = fast_exp2(mB - mnB);
            mA = mnA; mB = mnB;

            float psA = 0.0f, psB = 0.0f;
#pragma unroll
            for (int ni = 0; ni < 8; ni++) {
                float p0 = fast_exp2(s[ni][0] - mnA);
                float p1 = fast_exp2(s[ni][1] - mnA);
                float p2 = fast_exp2(s[ni][2] - mnB);
                float p3 = fast_exp2(s[ni][3] - mnB);
                psA += p0 + p1; psB += p2 + p3;
                s[ni][0] = p0; s[ni][1] = p1; s[ni][2] = p2; s[ni][3] = p3;
            }
            psA += __shfl_xor_sync(0xffffffffu, psA, 1);
            psA += __shfl_xor_sync(0xffffffffu, psA, 2);
            psB += __shfl_xor_sync(0xffffffffu, psB, 1);
            psB += __shfl_xor_sync(0xffffffffu, psB, 2);
            lAcc = lAcc * aAl + psA;
            lBcc = lBcc * aBl + psB;

#pragma unroll
            for (int ni = 0; ni < 8; ni++) {
                o[ni][0] *= aAl; o[ni][1] *= aAl;
                o[ni][2] *= aBl; o[ni][3] *= aBl;
            }

            // ---- O += P V (3xbf16), P in registers, V via ldsm.trans ----
#pragma unroll
            for (int j = 0; j < 4; j++) {   // k-step over 16 keys
                uint32_t pa_h[4], pa_l[4];
#pragma unroll
                for (int half = 0; half < 2; half++) {   // kblk 0 / 8
                    const float* sp = s[2 * j + half];
                    __nv_bfloat162 h0 = __floats2bfloat162_rn(sp[0], sp[1]);
                    __nv_bfloat162 h1 = __floats2bfloat162_rn(sp[2], sp[3]);
                    __nv_bfloat162 l0 = __floats2bfloat162_rn(
                        sp[0] - __bfloat162float(h0.x), sp[1] - __bfloat162float(h0.y));
                    __nv_bfloat162 l1 = __floats2bfloat162_rn(
                        sp[2] - __bfloat162float(h1.x), sp[3] - __bfloat162float(h1.y));
                    pa_h[half * 2 + 0] = *(uint32_t*)&h0;
                    pa_h[half * 2 + 1] = *(uint32_t*)&h1;
                    pa_l[half * 2 + 0] = *(uint32_t*)&l0;
                    pa_l[half * 2 + 1] = *(uint32_t*)&l1;
                }

                uint32_t vh[4][4], vl[4][4];
                const int vrow = j * 16 + koff;          // key row in V panel
                const uint32_t vro = (uint32_t)vrow * 128;
                const int v_rx = vrow & 7;
#pragma unroll
                for (int pi = 0; pi < 4; pi++) {
                    uint32_t chv = (uint32_t)(2 * pi + noct);
                    uint32_t bo = vro + ((chv ^ (uint32_t)v_rx) << 4);
                    ldsm_x4_trans(vh[pi], skv + 16384 + bo);   // V hi
                    ldsm_x4_trans(vl[pi], skv + 24576 + bo);   // V lo
                }
#pragma unroll
                for (int ni = 0; ni < 8; ni++) {
                    const int pi = ni >> 1, j0 = (ni & 1) * 2;
                    mma_bf16(o[ni], pa_l, vh[pi][j0], vh[pi][j0 + 1]);
                    mma_bf16(o[ni], pa_h, vl[pi][j0], vl[pi][j0 + 1]);
                    mma_bf16(o[ni], pa_h, vh[pi][j0], vh[pi][j0 + 1]);
                }
            }
        }
        __syncthreads();   // all warps done with buf[kt&1] before its reload
    }

    // ---- epilogue: normalize, split to bf16, write g_Yhi/lo [b][t][c] ----
    const float invA = 1.0f / lAcc;
    const float invB = 1.0f / lBcc;
    const int tA = qi * ABQ + warp * 16 + rA;
    const int tB = tA + 8;
    const size_t baseA = ((size_t)bb * TSEQ + tA) * CDIM + hh * DH;
    const size_t baseB = ((size_t)bb * TSEQ + tB) * CDIM + hh * DH;
#pragma unroll
    for (int ni = 0; ni < 8; ni++) {
        int col = ni * 8 + qcol;
        float yA0 = o[ni][0] * invA, yA1 = o[ni][1] * invA;
        float yB0 = o[ni][2] * invB, yB1 = o[ni][3] * invB;
        __nv_bfloat16 h0, l0, h1, l1;
        __nv_bfloat162 hv, lv;
        bsplit(yA0, h0, l0); bsplit(yA1, h1, l1);
        hv.x = h0; hv.y = h1; lv.x = l0; lv.y = l1;
        *(__nv_bfloat162*)(g_Yhi + baseA + col) = hv;
        *(__nv_bfloat162*)(g_Ylo + baseA + col) = lv;
        bsplit(yB0, h0, l0); bsplit(yB1, h1, l1);
        hv.x = h0; hv.y = h1; lv.x = l0; lv.y = l1;
        *(__nv_bfloat162*)(g_Yhi + baseB + col) = hv;
        *(__nv_bfloat162*)(g_Ylo + baseB + col) = lv;
    }
}

// ---------------------------------------------------------------------------
// Launch
// ---------------------------------------------------------------------------
extern "C" void kernel_launch(void* const* d_in, const int* in_sizes, int n_in,
                              void* d_out, int out_size)
{
    const float* x      = (const float*)d_in[0];
    const float* w_attn = (const float*)d_in[1];
    const float* b_attn = (const float*)d_in[2];
    const float* w_proj = (const float*)d_in[3];
    const float* b_proj = (const float*)d_in[4];
    float* out = (float*)d_out;

    // 0) Fused preprocessing (pure splits, no transpose)
    {
        preproc_kernel<<<8192, 256>>>(x, w_attn, w_proj);
    }

    // 1) QKV GEMM (3xbf16, trans-B) -> pre-split Q/K/V [bh][t][d]
    {
        cudaFuncSetAttribute(tc_gemm<3 * CDIM, 0>,
                             cudaFuncAttributeMaxDynamicSharedMemorySize, GSMEM);
        dim3 grid(3 * CDIM / GBN, MROWS / GBM);   // (24, 32)
        tc_gemm<3 * CDIM, 0><<<grid, 256, GSMEM>>>(b_attn, nullptr);
    }

    // 2) Tensor-core flash attention (3xbf16, trans-ldmatrix V)
    {
        cudaFuncSetAttribute(attn_kernel,
                             cudaFuncAttributeMaxDynamicSharedMemorySize, ASMEM);
        dim3 grid(TSEQ / ABQ, NB * NH);           // (8, 64)
        attn_kernel<<<grid, 256, ASMEM>>>();
    }

    // 3) Output projection (3xbf16, trans-B)
    {
        cudaFuncSetAttribute(tc_gemm<CDIM, 1>,
                             cudaFuncAttributeMaxDynamicSharedMemorySize, GSMEM);
        dim3 grid(CDIM / GBN, MROWS / GBM);       // (8, 32)
        tc_gemm<CDIM, 1><<<grid, 256, GSMEM>>>(b_proj, out);
    }
}

// round 13
// speedup vs baseline: 1.0603x; 1.0013x over previous
#include <cuda_runtime.h>
#include <cuda_bf16.h>
#include <math.h>
#include <stdint.h>

// Problem constants
#define NB    4
#define TSEQ  1024
#define CDIM  1024
#define NH    16
#define DH    64
#define MROWS (NB * TSEQ)      // 4096
#define KDIM  1024

// Scratch (device globals -- no allocation allowed)
__device__ __nv_bfloat16 g_Xhi[(size_t)MROWS * KDIM];
__device__ __nv_bfloat16 g_Xlo[(size_t)MROWS * KDIM];
__device__ __nv_bfloat16 g_Yhi[(size_t)MROWS * KDIM];
__device__ __nv_bfloat16 g_Ylo[(size_t)MROWS * KDIM];
__device__ __nv_bfloat16 g_WAhi[(size_t)KDIM * 3 * CDIM];   // w_attn [k][n] (natural)
__device__ __nv_bfloat16 g_WAlo[(size_t)KDIM * 3 * CDIM];
__device__ __nv_bfloat16 g_WPhi[(size_t)KDIM * CDIM];       // w_proj [k][n] (natural)
__device__ __nv_bfloat16 g_WPlo[(size_t)KDIM * CDIM];
__device__ __nv_bfloat16 g_Qh[(size_t)NB * NH * TSEQ * DH];
__device__ __nv_bfloat16 g_Qlo[(size_t)NB * NH * TSEQ * DH];
__device__ __nv_bfloat16 g_Kh[(size_t)NB * NH * TSEQ * DH];
__device__ __nv_bfloat16 g_Klo[(size_t)NB * NH * TSEQ * DH];
__device__ __nv_bfloat16 g_Vh[(size_t)NB * NH * TSEQ * DH];   // [bh][t][d]
__device__ __nv_bfloat16 g_Vlo[(size_t)NB * NH * TSEQ * DH];

// ---------------------------------------------------------------------------
// Helpers
// ---------------------------------------------------------------------------
__device__ __forceinline__ uint32_t smem_u32(const void* p) {
    return (uint32_t)__cvta_generic_to_shared(p);
}

__device__ __forceinline__ void cp_async16(uint32_t saddr, const void* gptr) {
    asm volatile("cp.async.cg.shared.global [%0], [%1], 16;" :: "r"(saddr), "l"(gptr));
}
#define CP_COMMIT() asm volatile("cp.async.commit_group;" ::: "memory")

__device__ __forceinline__ void ldsm_x4(uint32_t* r, uint32_t addr) {
    asm volatile("ldmatrix.sync.aligned.m8n8.x4.shared.b16 {%0,%1,%2,%3}, [%4];"
                 : "=r"(r[0]), "=r"(r[1]), "=r"(r[2]), "=r"(r[3]) : "r"(addr));
}

__device__ __forceinline__ void ldsm_x4_trans(uint32_t* r, uint32_t addr) {
    asm volatile("ldmatrix.sync.aligned.m8n8.x4.trans.shared.b16 {%0,%1,%2,%3}, [%4];"
                 : "=r"(r[0]), "=r"(r[1]), "=r"(r[2]), "=r"(r[3]) : "r"(addr));
}

__device__ __forceinline__ void mma_bf16(float* c, const uint32_t* a,
                                         uint32_t b0, uint32_t b1) {
    asm volatile(
        "mma.sync.aligned.m16n8k16.row.col.f32.bf16.bf16.f32 "
        "{%0,%1,%2,%3}, {%4,%5,%6,%7}, {%8,%9}, {%0,%1,%2,%3};"
        : "+f"(c[0]), "+f"(c[1]), "+f"(c[2]), "+f"(c[3])
        : "r"(a[0]), "r"(a[1]), "r"(a[2]), "r"(a[3]), "r"(b0), "r"(b1));
}

__device__ __forceinline__ void bsplit(float f, __nv_bfloat16& h, __nv_bfloat16& l) {
    h = __float2bfloat16_rn(f);
    l = __float2bfloat16_rn(f - __bfloat162float(h));
}

__device__ __forceinline__ float fast_exp2(float x) {
    float r;
    asm("ex2.approx.ftz.f32 %0, %1;" : "=f"(r) : "f"(x));
    return r;
}

// ---------------------------------------------------------------------------
// Fused preprocessing: pure elementwise bf16 split (NO transposes).
// ---------------------------------------------------------------------------
__device__ __forceinline__ void split4(const float* __restrict__ s,
        __nv_bfloat16* dh, __nv_bfloat16* dl, size_t i)
{
    float4 v = *(const float4*)(s + i);
    __nv_bfloat16 h0, l0, h1, l1, h2, l2, h3, l3;
    bsplit(v.x, h0, l0); bsplit(v.y, h1, l1);
    bsplit(v.z, h2, l2); bsplit(v.w, h3, l3);
    __nv_bfloat162* ph = (__nv_bfloat162*)(dh + i);
    __nv_bfloat162* pl = (__nv_bfloat162*)(dl + i);
    __nv_bfloat162 a; a.x = h0; a.y = h1;
    __nv_bfloat162 b; b.x = h2; b.y = h3;
    ph[0] = a; ph[1] = b;
    a.x = l0; a.y = l1; b.x = l2; b.y = l3;
    pl[0] = a; pl[1] = b;
}

__global__ __launch_bounds__(256) void preproc_kernel(const float* __restrict__ x,
        const float* __restrict__ wa, const float* __restrict__ wp)
{
    const int bid = blockIdx.x;
    const int tid = threadIdx.x;
    if (bid < 3072) {
        size_t i = ((size_t)bid * 256 + tid) * 4;
        split4(wa, g_WAhi, g_WAlo, i);
    } else if (bid < 4096) {
        size_t i = ((size_t)(bid - 3072) * 256 + tid) * 4;
        split4(wp, g_WPhi, g_WPlo, i);
    } else {
        size_t i = ((size_t)(bid - 4096) * 256 + tid) * 4;
        split4(x, g_Xhi, g_Xlo, i);
    }
}

// ---------------------------------------------------------------------------
// 3xBF16 mma.sync GEMM. A: [m][k] hi/lo; B: natural [k][n] hi/lo via
// ldmatrix.trans. BK=32, 3 stages, 2 CTAs/SM. Mainloop: pi-chunked
// fragment interleave (B frags loaded per-chunk right before their MMAs).
// ---------------------------------------------------------------------------
#define GBM 128
#define GBN 128
#define GBK 32
#define KTILES  (KDIM / GBK)            // 32
#define PANEL   8192
#define STAGE   (4 * PANEL)              // 32768
#define GSMEM   (3 * STAGE)              // 98304
#define OAH 0
#define OAL 8192
#define OBH 16384
#define OBL 24576

__device__ __forceinline__ uint32_t sw64(int row, int ch) {
    return (uint32_t)row * 64 + (uint32_t)((ch ^ ((row >> 1) & 3)) << 4);
}
__device__ __forceinline__ uint32_t swB(int row, int ch) {
    return (uint32_t)row * 256 + (uint32_t)((ch ^ (row & 15)) << 4);
}

template <int N>
__device__ __forceinline__ void load_tile_b(uint32_t sg,
        const __nv_bfloat16* Ah, const __nv_bfloat16* Al,
        const __nv_bfloat16* Bh, const __nv_bfloat16* Bl,
        int k0, int tid)
{
#pragma unroll
    for (int l = 0; l < 8; l++) {
        int idx = tid + l * 256;          // 0..2047
        if (idx < 1024) {
            int panel = idx >> 9;
            int rem = idx & 511;
            int row = rem >> 2;
            int ch  = rem & 3;
            cp_async16(sg + (panel ? OAL : OAH) + sw64(row, ch),
                       (panel ? Al : Ah) + (size_t)row * KDIM + k0 + ch * 8);
        } else {
            int panel = (idx - 1024) >> 9;
            int rem = idx & 511;
            int row = rem >> 4;
            int ch  = rem & 15;
            cp_async16(sg + (panel ? OBL : OBH) + swB(row, ch),
                       (panel ? Bl : Bh) + (size_t)(k0 + row) * N + ch * 8);
        }
    }
}

template <int N, int MODE>
__global__ __launch_bounds__(256, 2) void tc_gemm(const float* __restrict__ bias,
                                                  float* __restrict__ out)
{
    extern __shared__ char smem[];
    const uint32_t sbase = smem_u32(smem);
    const int tid  = threadIdx.x;
    const int warp = tid >> 5;
    const int lane = tid & 31;
    const int wm = warp >> 1;             // 0..3
    const int wn = warp & 1;              // 0..1
    const int bm = blockIdx.y * GBM;
    const int bn = blockIdx.x * GBN;

    const __nv_bfloat16* Ah = ((MODE == 0) ? g_Xhi : g_Yhi) + (size_t)bm * KDIM;
    const __nv_bfloat16* Al = ((MODE == 0) ? g_Xlo : g_Ylo) + (size_t)bm * KDIM;
    const __nv_bfloat16* Bh = ((MODE == 0) ? g_WAhi : g_WPhi) + bn;
    const __nv_bfloat16* Bl = ((MODE == 0) ? g_WAlo : g_WPlo) + bn;

    const int arow = wm * 32 + (lane & 15);
    const int acb = (lane >> 4) & 1;
    const int koffG = (((lane >> 3) & 1) << 3) + (lane & 7);
    const int noctG = lane >> 4;

    float acc[2][8][4];
#pragma unroll
    for (int mi = 0; mi < 2; mi++)
#pragma unroll
        for (int ni = 0; ni < 8; ni++)
#pragma unroll
            for (int r = 0; r < 4; r++) acc[mi][ni][r] = 0.0f;

#pragma unroll
    for (int t = 0; t < 2; t++) {
        load_tile_b<N>(sbase + t * STAGE, Ah, Al, Bh, Bl, t * GBK, tid);
        CP_COMMIT();
    }

    for (int t = 0; t < KTILES; t++) {
        if (t < KTILES - 2)
            asm volatile("cp.async.wait_group 1;" ::: "memory");
        else
            asm volatile("cp.async.wait_group 0;" ::: "memory");
        __syncthreads();

        const uint32_t sg = sbase + (uint32_t)(t % 3) * STAGE;

#pragma unroll
        for (int ks = 0; ks < 2; ks++) {
            uint32_t ah[2][4], al[2][4];
#pragma unroll
            for (int mi = 0; mi < 2; mi++) {
                uint32_t ao = sw64(arow + mi * 16, ks * 2 + acb);
                ldsm_x4(ah[mi], sg + OAH + ao);
                ldsm_x4(al[mi], sg + OAL + ao);
            }
            // pi-chunked: load one B fragment pair, immediately use it.
#pragma unroll
            for (int pi = 0; pi < 4; pi++) {
                uint32_t bh[4], bl[4];
                int vr = ks * 16 + koffG;
                int chv = wn * 8 + 2 * pi + noctG;
                uint32_t bo = swB(vr, chv);
                ldsm_x4_trans(bh, sg + OBH + bo);
                ldsm_x4_trans(bl, sg + OBL + bo);
#pragma unroll
                for (int mi = 0; mi < 2; mi++)
#pragma unroll
                    for (int sub = 0; sub < 2; sub++) {
                        const int ni = pi * 2 + sub;
                        const int j0 = sub * 2;
                        mma_bf16(acc[mi][ni], al[mi], bh[j0], bh[j0 + 1]);
                        mma_bf16(acc[mi][ni], ah[mi], bl[j0], bl[j0 + 1]);
                        mma_bf16(acc[mi][ni], ah[mi], bh[j0], bh[j0 + 1]);
                    }
            }
        }

        if (t + 2 < KTILES) {
            load_tile_b<N>(sbase + (uint32_t)((t + 2) % 3) * STAGE,
                           Ah, Al, Bh, Bl, (t + 2) * GBK, tid);
            CP_COMMIT();
        }
    }

    // Epilogue
#pragma unroll
    for (int mi = 0; mi < 2; mi++) {
#pragma unroll
        for (int ni = 0; ni < 8; ni++) {
            const int col = bn + wn * 64 + ni * 8 + (lane & 3) * 2;
            float2 bv = *(const float2*)(bias + col);
#pragma unroll
            for (int half = 0; half < 2; half++) {
                const int row = bm + wm * 32 + mi * 16 + (lane >> 2) + half * 8;
                float vx = acc[mi][ni][half * 2 + 0] + bv.x;
                float vy = acc[mi][ni][half * 2 + 1] + bv.y;
                if (MODE == 0) {
                    const int sec  = col >> 10;          // 0=q, 1=k, 2=v
                    const int cc   = col & 1023;
                    const int head = cc >> 6;
                    const int dpos = cc & 63;
                    const int b  = row >> 10;
                    const int tt = row & 1023;
                    const int bh2 = b * NH + head;
                    __nv_bfloat16 hx, lx, hy, ly;
                    bsplit(vx, hx, lx); bsplit(vy, hy, ly);
                    __nv_bfloat16* dh = (sec == 0) ? g_Qh : (sec == 1) ? g_Kh : g_Vh;
                    __nv_bfloat16* dl = (sec == 0) ? g_Qlo : (sec == 1) ? g_Klo : g_Vlo;
                    size_t o = ((size_t)bh2 * TSEQ + tt) * DH + dpos;
                    __nv_bfloat162 hv; hv.x = hx; hv.y = hy;
                    __nv_bfloat162 lv; lv.x = lx; lv.y = ly;
                    *(__nv_bfloat162*)(dh + o) = hv;
                    *(__nv_bfloat162*)(dl + o) = lv;
                } else {
                    float2 v2; v2.x = vx; v2.y = vy;
                    *(float2*)(out + (size_t)row * N + col) = v2;
                }
            }
        }
    }
}

// ---------------------------------------------------------------------------
// Tensor-core flash attention, 3xBF16, register-resident P, double-buffered
// K/V, trans-ldmatrix V. (unchanged from R12)
// ---------------------------------------------------------------------------
#define ABQ   128
#define ABK   64
#define SQH 0
#define SQL 16384
#define SKV 32768          // stage s at SKV + s*32768: {KH 0, KL 8K, VH 16K, VL 24K}
#define ASMEM 98304

__device__ __forceinline__ void attn_load_kv(uint32_t sbuf,
        const __nv_bfloat16* Khp, const __nv_bfloat16* Klp,
        const __nv_bfloat16* Vhp, const __nv_bfloat16* Vlp,
        int k0, int tid)
{
#pragma unroll
    for (int l = 0; l < 4; l++) {
        int idx = tid + l * 256;
        int panel = idx >> 9;            // 0 = hi, 1 = lo
        int rem = idx & 511;
        int r = rem >> 3, ch = rem & 7;
        uint32_t off = (uint32_t)r * 128 + ch * 16;
        uint32_t sw = off ^ ((off >> 3) & 0x70);
        cp_async16(sbuf + (panel ? 8192 : 0) + sw,
                   (panel ? Klp : Khp) + (size_t)(k0 + r) * DH + ch * 8);
        cp_async16(sbuf + (panel ? 24576 : 16384) + sw,
                   (panel ? Vlp : Vhp) + (size_t)(k0 + r) * DH + ch * 8);
    }
}

__global__ __launch_bounds__(256, 2) void attn_kernel()
{
    extern __shared__ char smc[];
    const uint32_t sb = smem_u32(smc);

    const int qi = gridDim.x - 1 - blockIdx.x;   // heavy tiles first
    const int bh = blockIdx.y;
    const int bb = bh >> 4, hh = bh & 15;
    const __nv_bfloat16* Qhp = g_Qh  + (size_t)bh * TSEQ * DH;
    const __nv_bfloat16* Qlp = g_Qlo + (size_t)bh * TSEQ * DH;
    const __nv_bfloat16* Khp = g_Kh  + (size_t)bh * TSEQ * DH;
    const __nv_bfloat16* Klp = g_Klo + (size_t)bh * TSEQ * DH;
    const __nv_bfloat16* Vhp = g_Vh  + (size_t)bh * TSEQ * DH;
    const __nv_bfloat16* Vlp = g_Vlo + (size_t)bh * TSEQ * DH;

    const int tid  = threadIdx.x;
    const int warp = tid >> 5;
    const int lane = tid & 31;
    const int rA   = lane >> 2;
    const int qcol = (lane & 3) * 2;

    const int acb  = (lane >> 4) & 1;
    const int bcb  = (lane >> 3) & 1;
    const int brow = (lane & 7) + ((lane & 16) >> 1);
    const int koff = (((lane >> 3) & 1) << 3) + (lane & 7);
    const int noct = lane >> 4;

    // Q panels (hi+lo): committed together with K/V tile 0
#pragma unroll
    for (int l = 0; l < 8; l++) {
        int idx = tid + l * 256;
        int panel = idx >> 10;
        int rem = idx & 1023;
        int r = rem >> 3, ch = rem & 7;
        uint32_t off = (uint32_t)r * 128 + ch * 16;
        uint32_t sw = off ^ ((off >> 3) & 0x70);
        const __nv_bfloat16* src = (panel ? Qlp : Qhp) + (size_t)(qi * ABQ + r) * DH + ch * 8;
        cp_async16(sb + (panel ? SQL : SQH) + sw, src);
    }
    attn_load_kv(sb + SKV, Khp, Klp, Vhp, Vlp, 0, tid);
    CP_COMMIT();

    float o[8][4];
#pragma unroll
    for (int ni = 0; ni < 8; ni++)
#pragma unroll
        for (int j = 0; j < 4; j++) o[ni][j] = 0.0f;
    float mA = -1e30f, mB = -1e30f, lAcc = 0.0f, lBcc = 0.0f;

    const float CS = 0.18033688011112042f;   // 0.125 * log2(e)
    const int ntiles = 2 * qi + 2;

    for (int kt = 0; kt < ntiles; kt++) {
        if (kt + 1 < ntiles) {
            attn_load_kv(sb + SKV + ((kt + 1) & 1) * 32768,
                         Khp, Klp, Vhp, Vlp, (kt + 1) * ABK, tid);
            CP_COMMIT();
            asm volatile("cp.async.wait_group 1;" ::: "memory");
        } else {
            asm volatile("cp.async.wait_group 0;" ::: "memory");
        }
        __syncthreads();

        const uint32_t skv = sb + SKV + (uint32_t)(kt & 1) * 32768;

        if (kt * ABK <= qi * ABQ + warp * 16 + 15) {
            // ---- S = Q K^T (3xbf16) ----
            float s[8][4];
#pragma unroll
            for (int ni = 0; ni < 8; ni++)
#pragma unroll
                for (int j = 0; j < 4; j++) s[ni][j] = 0.0f;

            const int aQrow = warp * 16 + (lane & 15);
            const uint32_t a_ro = (uint32_t)aQrow * 128;
            const int a_rx = aQrow & 7;
#pragma unroll
            for (int ks = 0; ks < 4; ks++) {
                uint32_t ah[4], al[4], kh[4][4], kl[4][4];
                uint32_t ao = a_ro + (uint32_t)(((ks * 2 + acb) ^ a_rx) << 4);
                ldsm_x4(ah, sb + SQH + ao);
                ldsm_x4(al, sb + SQL + ao);
#pragma unroll
                for (int pi = 0; pi < 4; pi++) {
                    int br = pi * 16 + brow;
                    uint32_t bo = (uint32_t)br * 128 +
                                  (uint32_t)(((ks * 2 + bcb) ^ (br & 7)) << 4);
                    ldsm_x4(kh[pi], skv + bo);           // K hi
                    ldsm_x4(kl[pi], skv + 8192 + bo);    // K lo
                }
#pragma unroll
                for (int ni = 0; ni < 8; ni++) {
                    const int pi = ni >> 1, j0 = (ni & 1) * 2;
                    mma_bf16(s[ni], al, kh[pi][j0], kh[pi][j0 + 1]);
                    mma_bf16(s[ni], ah, kl[pi][j0], kl[pi][j0 + 1]);
                    mma_bf16(s[ni], ah, kh[pi][j0], kh[pi][j0 + 1]);
                }
            }

            // ---- scale + causal mask ----
            const bool needmask = (kt * ABK + ABK - 1 > qi * ABQ + warp * 16);
            const int rowgA = qi * ABQ + warp * 16 + rA;
            const int rowgB = rowgA + 8;
            const int cb = kt * ABK + qcol;
#pragma unroll
            for (int ni = 0; ni < 8; ni++) {
                float z0 = s[ni][0] * CS, z1 = s[ni][1] * CS;
                float z2 = s[ni][2] * CS, z3 = s[ni][3] * CS;
                if (needmask) {
                    int c0 = cb + ni * 8, c1 = c0 + 1;
                    if (c0 > rowgA) z0 = -1e30f;
                    if (c1 > rowgA) z1 = -1e30f;
                    if (c0 > rowgB) z2 = -1e30f;
                    if (c1 > rowgB) z3 = -1e30f;
                }
                s[ni][0] = z0; s[ni][1] = z1; s[ni][2] = z2; s[ni][3] = z3;
            }

            // ---- online softmax ----
            float mtA = -1e30f, mtB = -1e30f;
#pragma unroll
            for (int ni = 0; ni < 8; ni++) {
                mtA = fmaxf(mtA, fmaxf(s[ni][0], s[ni][1]));
                mtB = fmaxf(mtB, fmaxf(s[ni][2], s[ni][3]));
            }
            mtA = fmaxf(mtA, __shfl_xor_sync(0xffffffffu, mtA, 1));
            mtA = fmaxf(mtA, __shfl_xor_sync(0xffffffffu, mtA, 2));
            mtB = fmaxf(mtB, __shfl_xor_sync(0xffffffffu, mtB, 1));
            mtB = fmaxf(mtB, __shfl_xor_sync(0xffffffffu, mtB, 2));

            const float mnA = fmaxf(mA, mtA);
            const float mnB = fmaxf(mB, mtB);
            const float aAl = fast_exp2(mA - mnA);
            const float aBl = fast_exp2(mB - mnB);
            mA = mnA; mB = mnB;

            float psA = 0.0f, psB = 0.0f;
#pragma unroll
            for (int ni = 0; ni < 8; ni++) {
                float p0 = fast_exp2(s[ni][0] - mnA);
                float p1 = fast_exp2(s[ni][1] - mnA);
                float p2 = fast_exp2(s[ni][2] - mnB);
                float p3 = fast_exp2(s[ni][3] - mnB);
                psA += p0 + p1; psB += p2 + p3;
                s[ni][0] = p0; s[ni][1] = p1; s[ni][2] = p2; s[ni][3] = p3;
            }
            psA += __shfl_xor_sync(0xffffffffu, psA, 1);
            psA += __shfl_xor_sync(0xffffffffu, psA, 2);
            psB += __shfl_xor_sync(0xffffffffu, psB, 1);
            psB += __shfl_xor_sync(0xffffffffu, psB, 2);
            lAcc = lAcc * aAl + psA;
            lBcc = lBcc * aBl + psB;

#pragma unroll
            for (int ni = 0; ni < 8; ni++) {
                o[ni][0] *= aAl; o[ni][1] *= aAl;
                o[ni][2] *= aBl; o[ni][3] *= aBl;
            }

            // ---- O += P V (3xbf16), P in registers, V via ldsm.trans ----
#pragma unroll
            for (int j = 0; j < 4; j++) {   // k-step over 16 keys
                uint32_t pa_h[4], pa_l[4];
#pragma unroll
                for (int half = 0; half < 2; half++) {   // kblk 0 / 8
                    const float* sp = s[2 * j + half];
                    __nv_bfloat162 h0 = __floats2bfloat162_rn(sp[0], sp[1]);
                    __nv_bfloat162 h1 = __floats2bfloat162_rn(sp[2], sp[3]);
                    __nv_bfloat162 l0 = __floats2bfloat162_rn(
                        sp[0] - __bfloat162float(h0.x), sp[1] - __bfloat162float(h0.y));
                    __nv_bfloat162 l1 = __floats2bfloat162_rn(
                        sp[2] - __bfloat162float(h1.x), sp[3] - __bfloat162float(h1.y));
                    pa_h[half * 2 + 0] = *(uint32_t*)&h0;
                    pa_h[half * 2 + 1] = *(uint32_t*)&h1;
                    pa_l[half * 2 + 0] = *(uint32_t*)&l0;
                    pa_l[half * 2 + 1] = *(uint32_t*)&l1;
                }

                uint32_t vh[4][4], vl[4][4];
                const int vrow = j * 16 + koff;          // key row in V panel
                const uint32_t vro = (uint32_t)vrow * 128;
                const int v_rx = vrow & 7;
#pragma unroll
                for (int pi = 0; pi < 4; pi++) {
                    uint32_t chv = (uint32_t)(2 * pi + noct);
                    uint32_t bo = vro + ((chv ^ (uint32_t)v_rx) << 4);
                    ldsm_x4_trans(vh[pi], skv + 16384 + bo);   // V hi
                    ldsm_x4_trans(vl[pi], skv + 24576 + bo);   // V lo
                }
#pragma unroll
                for (int ni = 0; ni < 8; ni++) {
                    const int pi = ni >> 1, j0 = (ni & 1) * 2;
                    mma_bf16(o[ni], pa_l, vh[pi][j0], vh[pi][j0 + 1]);
                    mma_bf16(o[ni], pa_h, vl[pi][j0], vl[pi][j0 + 1]);
                    mma_bf16(o[ni], pa_h, vh[pi][j0], vh[pi][j0 + 1]);
                }
            }
        }
        __syncthreads();   // all warps done with buf[kt&1] before its reload
    }

    // ---- epilogue: normalize, split to bf16, write g_Yhi/lo [b][t][c] ----
    const float invA = 1.0f / lAcc;
    const float invB = 1.0f / lBcc;
    const int tA = qi * ABQ + warp * 16 + rA;
    const int tB = tA + 8;
    const size_t baseA = ((size_t)bb * TSEQ + tA) * CDIM + hh * DH;
    const size_t baseB = ((size_t)bb * TSEQ + tB) * CDIM + hh * DH;
#pragma unroll
    for (int ni = 0; ni < 8; ni++) {
        int col = ni * 8 + qcol;
        float yA0 = o[ni][0] * invA, yA1 = o[ni][1] * invA;
        float yB0 = o[ni][2] * invB, yB1 = o[ni][3] * invB;
        __nv_bfloat16 h0, l0, h1, l1;
        __nv_bfloat162 hv, lv;
        bsplit(yA0, h0, l0); bsplit(yA1, h1, l1);
        hv.x = h0; hv.y = h1; lv.x = l0; lv.y = l1;
        *(__nv_bfloat162*)(g_Yhi + baseA + col) = hv;
        *(__nv_bfloat162*)(g_Ylo + baseA + col) = lv;
        bsplit(yB0, h0, l0); bsplit(yB1, h1, l1);
        hv.x = h0; hv.y = h1; lv.x = l0; lv.y = l1;
        *(__nv_bfloat162*)(g_Yhi + baseB + col) = hv;
        *(__nv_bfloat162*)(g_Ylo + baseB + col) = lv;
    }
}

// ---------------------------------------------------------------------------
// Launch
// ---------------------------------------------------------------------------
extern "C" void kernel_launch(void* const* d_in, const int* in_sizes, int n_in,
                              void* d_out, int out_size)
{
    const float* x      = (const float*)d_in[0];
    const float* w_attn = (const float*)d_in[1];
    const float* b_attn = (const float*)d_in[2];
    const float* w_proj = (const float*)d_in[3];
    const float* b_proj = (const float*)d_in[4];
    float* out = (float*)d_out;

    // 0) Fused preprocessing (pure splits, no transpose)
    {
        preproc_kernel<<<8192, 256>>>(x, w_attn, w_proj);
    }

    // 1) QKV GEMM (3xbf16, trans-B) -> pre-split Q/K/V [bh][t][d]
    {
        cudaFuncSetAttribute(tc_gemm<3 * CDIM, 0>,
                             cudaFuncAttributeMaxDynamicSharedMemorySize, GSMEM);
        dim3 grid(3 * CDIM / GBN, MROWS / GBM);   // (24, 32)
        tc_gemm<3 * CDIM, 0><<<grid, 256, GSMEM>>>(b_attn, nullptr);
    }

    // 2) Tensor-core flash attention (3xbf16, trans-ldmatrix V)
    {
        cudaFuncSetAttribute(attn_kernel,
                             cudaFuncAttributeMaxDynamicSharedMemorySize, ASMEM);
        dim3 grid(TSEQ / ABQ, NB * NH);           // (8, 64)
        attn_kernel<<<grid, 256, ASMEM>>>();
    }

    // 3) Output projection (3xbf16, trans-B)
    {
        cudaFuncSetAttribute(tc_gemm<CDIM, 1>,
                             cudaFuncAttributeMaxDynamicSharedMemorySize, GSMEM);
        dim3 grid(CDIM / GBN, MROWS / GBM);       // (8, 32)
        tc_gemm<CDIM, 1><<<grid, 256, GSMEM>>>(b_proj, out);
    }
}

// round 14
// speedup vs baseline: 1.0686x; 1.0078x over previous
#include <cuda_runtime.h>
#include <cuda_bf16.h>
#include <math.h>
#include <stdint.h>

// Problem constants
#define NB    4
#define TSEQ  1024
#define CDIM  1024
#define NH    16
#define DH    64
#define MROWS (NB * TSEQ)      // 4096
#define KDIM  1024

// Scratch (device globals -- no allocation allowed)
__device__ __nv_bfloat16 g_Xhi[(size_t)MROWS * KDIM];
__device__ __nv_bfloat16 g_Xlo[(size_t)MROWS * KDIM];
__device__ __nv_bfloat16 g_Yhi[(size_t)MROWS * KDIM];
__device__ __nv_bfloat16 g_Ylo[(size_t)MROWS * KDIM];
__device__ __nv_bfloat16 g_WAhi[(size_t)KDIM * 3 * CDIM];   // w_attn [k][n] (natural)
__device__ __nv_bfloat16 g_WAlo[(size_t)KDIM * 3 * CDIM];
__device__ __nv_bfloat16 g_WPhi[(size_t)KDIM * CDIM];       // w_proj [k][n] (natural)
__device__ __nv_bfloat16 g_WPlo[(size_t)KDIM * CDIM];
__device__ __nv_bfloat16 g_Qh[(size_t)NB * NH * TSEQ * DH];
__device__ __nv_bfloat16 g_Qlo[(size_t)NB * NH * TSEQ * DH];
__device__ __nv_bfloat16 g_Kh[(size_t)NB * NH * TSEQ * DH];
__device__ __nv_bfloat16 g_Klo[(size_t)NB * NH * TSEQ * DH];
__device__ __nv_bfloat16 g_Vh[(size_t)NB * NH * TSEQ * DH];   // [bh][t][d]
__device__ __nv_bfloat16 g_Vlo[(size_t)NB * NH * TSEQ * DH];

// ---------------------------------------------------------------------------
// Helpers
// ---------------------------------------------------------------------------
__device__ __forceinline__ uint32_t smem_u32(const void* p) {
    return (uint32_t)__cvta_generic_to_shared(p);
}

__device__ __forceinline__ void cp_async16(uint32_t saddr, const void* gptr) {
    asm volatile("cp.async.cg.shared.global [%0], [%1], 16;" :: "r"(saddr), "l"(gptr));
}
#define CP_COMMIT() asm volatile("cp.async.commit_group;" ::: "memory")

__device__ __forceinline__ void ldsm_x4(uint32_t* r, uint32_t addr) {
    asm volatile("ldmatrix.sync.aligned.m8n8.x4.shared.b16 {%0,%1,%2,%3}, [%4];"
                 : "=r"(r[0]), "=r"(r[1]), "=r"(r[2]), "=r"(r[3]) : "r"(addr));
}

__device__ __forceinline__ void ldsm_x4_trans(uint32_t* r, uint32_t addr) {
    asm volatile("ldmatrix.sync.aligned.m8n8.x4.trans.shared.b16 {%0,%1,%2,%3}, [%4];"
                 : "=r"(r[0]), "=r"(r[1]), "=r"(r[2]), "=r"(r[3]) : "r"(addr));
}

__device__ __forceinline__ void mma_bf16(float* c, const uint32_t* a,
                                         uint32_t b0, uint32_t b1) {
    asm volatile(
        "mma.sync.aligned.m16n8k16.row.col.f32.bf16.bf16.f32 "
        "{%0,%1,%2,%3}, {%4,%5,%6,%7}, {%8,%9}, {%0,%1,%2,%3};"
        : "+f"(c[0]), "+f"(c[1]), "+f"(c[2]), "+f"(c[3])
        : "r"(a[0]), "r"(a[1]), "r"(a[2]), "r"(a[3]), "r"(b0), "r"(b1));
}

__device__ __forceinline__ void bsplit(float f, __nv_bfloat16& h, __nv_bfloat16& l) {
    h = __float2bfloat16_rn(f);
    l = __float2bfloat16_rn(f - __bfloat162float(h));
}

__device__ __forceinline__ float fast_exp2(float x) {
    float r;
    asm("ex2.approx.ftz.f32 %0, %1;" : "=f"(r) : "f"(x));
    return r;
}

// ---------------------------------------------------------------------------
// Fused preprocessing: pure elementwise bf16 split (NO transposes).
// ---------------------------------------------------------------------------
__device__ __forceinline__ void split4(const float* __restrict__ s,
        __nv_bfloat16* dh, __nv_bfloat16* dl, size_t i)
{
    float4 v = *(const float4*)(s + i);
    __nv_bfloat16 h0, l0, h1, l1, h2, l2, h3, l3;
    bsplit(v.x, h0, l0); bsplit(v.y, h1, l1);
    bsplit(v.z, h2, l2); bsplit(v.w, h3, l3);
    __nv_bfloat162* ph = (__nv_bfloat162*)(dh + i);
    __nv_bfloat162* pl = (__nv_bfloat162*)(dl + i);
    __nv_bfloat162 a; a.x = h0; a.y = h1;
    __nv_bfloat162 b; b.x = h2; b.y = h3;
    ph[0] = a; ph[1] = b;
    a.x = l0; a.y = l1; b.x = l2; b.y = l3;
    pl[0] = a; pl[1] = b;
}

__global__ __launch_bounds__(256) void preproc_kernel(const float* __restrict__ x,
        const float* __restrict__ wa, const float* __restrict__ wp)
{
    const int bid = blockIdx.x;
    const int tid = threadIdx.x;
    if (bid < 3072) {
        size_t i = ((size_t)bid * 256 + tid) * 4;
        split4(wa, g_WAhi, g_WAlo, i);
    } else if (bid < 4096) {
        size_t i = ((size_t)(bid - 3072) * 256 + tid) * 4;
        split4(wp, g_WPhi, g_WPlo, i);
    } else {
        size_t i = ((size_t)(bid - 4096) * 256 + tid) * 4;
        split4(x, g_Xhi, g_Xlo, i);
    }
}

// ---------------------------------------------------------------------------
// 3xBF16 mma.sync GEMM. BM=128, BN=64, BK=32, 3 stages = 72KB -> 3 CTAs/SM.
// A: [m][k] hi/lo; B: natural [k][n] hi/lo via ldmatrix.trans.
// 8 warps (4m x 2n), warp tile 32x32 (acc 32 regs).
// ---------------------------------------------------------------------------
#define GBM 128
#define GBN 64
#define GBK 32
#define KTILES  (KDIM / GBK)            // 32
#define APANEL  8192                     // 128r x 64B
#define BPANEL  4096                     // 32r x 128B
#define STAGE   (2 * APANEL + 2 * BPANEL)   // 24576
#define GSMEM   (3 * STAGE)                 // 73728
#define OAH 0
#define OAL 8192
#define OBH 16384
#define OBL 20480

__device__ __forceinline__ uint32_t sw64(int row, int ch) {
    return (uint32_t)row * 64 + (uint32_t)((ch ^ ((row >> 1) & 3)) << 4);
}
// B panel: 128B rows (8 chunks), chunk ^= row&7 -> conflict-free trans phases
__device__ __forceinline__ uint32_t swB(int row, int ch) {
    return (uint32_t)row * 128 + (uint32_t)((ch ^ (row & 7)) << 4);
}

template <int N>
__device__ __forceinline__ void load_tile_b(uint32_t sg,
        const __nv_bfloat16* Ah, const __nv_bfloat16* Al,
        const __nv_bfloat16* Bh, const __nv_bfloat16* Bl,
        int k0, int tid)
{
#pragma unroll
    for (int l = 0; l < 6; l++) {
        int idx = tid + l * 256;          // 0..1535
        if (idx < 1024) {
            int panel = idx >> 9;
            int rem = idx & 511;
            int row = rem >> 2;
            int ch  = rem & 3;
            cp_async16(sg + (panel ? OAL : OAH) + sw64(row, ch),
                       (panel ? Al : Ah) + (size_t)row * KDIM + k0 + ch * 8);
        } else {
            int rem = idx - 1024;          // 0..511
            int panel = rem >> 8;
            int rem2 = rem & 255;
            int row = rem2 >> 3;           // 0..31 (k)
            int ch  = rem2 & 7;            // n chunk
            cp_async16(sg + (panel ? OBL : OBH) + swB(row, ch),
                       (panel ? Bl : Bh) + (size_t)(k0 + row) * N + ch * 8);
        }
    }
}

template <int N, int MODE>
__global__ __launch_bounds__(256, 3) void tc_gemm(const float* __restrict__ bias,
                                                  float* __restrict__ out)
{
    extern __shared__ char smem[];
    const uint32_t sbase = smem_u32(smem);
    const int tid  = threadIdx.x;
    const int warp = tid >> 5;
    const int lane = tid & 31;
    const int wm = warp >> 1;             // 0..3
    const int wn = warp & 1;              // 0..1
    const int bm = blockIdx.y * GBM;
    const int bn = blockIdx.x * GBN;

    const __nv_bfloat16* Ah = ((MODE == 0) ? g_Xhi : g_Yhi) + (size_t)bm * KDIM;
    const __nv_bfloat16* Al = ((MODE == 0) ? g_Xlo : g_Ylo) + (size_t)bm * KDIM;
    const __nv_bfloat16* Bh = ((MODE == 0) ? g_WAhi : g_WPhi) + bn;
    const __nv_bfloat16* Bl = ((MODE == 0) ? g_WAlo : g_WPlo) + bn;

    const int arow = wm * 32 + (lane & 15);
    const int acb = (lane >> 4) & 1;
    const int koffG = (((lane >> 3) & 1) << 3) + (lane & 7);
    const int noctG = lane >> 4;

    float acc[2][4][4];
#pragma unroll
    for (int mi = 0; mi < 2; mi++)
#pragma unroll
        for (int ni = 0; ni < 4; ni++)
#pragma unroll
            for (int r = 0; r < 4; r++) acc[mi][ni][r] = 0.0f;

#pragma unroll
    for (int t = 0; t < 2; t++) {
        load_tile_b<N>(sbase + t * STAGE, Ah, Al, Bh, Bl, t * GBK, tid);
        CP_COMMIT();
    }

    for (int t = 0; t < KTILES; t++) {
        if (t < KTILES - 2)
            asm volatile("cp.async.wait_group 1;" ::: "memory");
        else
            asm volatile("cp.async.wait_group 0;" ::: "memory");
        __syncthreads();

        const uint32_t sg = sbase + (uint32_t)(t % 3) * STAGE;

#pragma unroll
        for (int ks = 0; ks < 2; ks++) {
            uint32_t ah[2][4], al[2][4];
#pragma unroll
            for (int mi = 0; mi < 2; mi++) {
                uint32_t ao = sw64(arow + mi * 16, ks * 2 + acb);
                ldsm_x4(ah[mi], sg + OAH + ao);
                ldsm_x4(al[mi], sg + OAL + ao);
            }
#pragma unroll
            for (int pi = 0; pi < 2; pi++) {
                uint32_t bh[4], bl[4];
                int vr = ks * 16 + koffG;
                int chv = wn * 4 + 2 * pi + noctG;
                uint32_t bo = swB(vr, chv);
                ldsm_x4_trans(bh, sg + OBH + bo);
                ldsm_x4_trans(bl, sg + OBL + bo);
#pragma unroll
                for (int mi = 0; mi < 2; mi++)
#pragma unroll
                    for (int sub = 0; sub < 2; sub++) {
                        const int ni = pi * 2 + sub;
                        const int j0 = sub * 2;
                        mma_bf16(acc[mi][ni], al[mi], bh[j0], bh[j0 + 1]);
                        mma_bf16(acc[mi][ni], ah[mi], bl[j0], bl[j0 + 1]);
                        mma_bf16(acc[mi][ni], ah[mi], bh[j0], bh[j0 + 1]);
                    }
            }
        }

        if (t + 2 < KTILES) {
            load_tile_b<N>(sbase + (uint32_t)((t + 2) % 3) * STAGE,
                           Ah, Al, Bh, Bl, (t + 2) * GBK, tid);
            CP_COMMIT();
        }
    }

    // Epilogue
#pragma unroll
    for (int mi = 0; mi < 2; mi++) {
#pragma unroll
        for (int ni = 0; ni < 4; ni++) {
            const int col = bn + wn * 32 + ni * 8 + (lane & 3) * 2;
            float2 bv = *(const float2*)(bias + col);
#pragma unroll
            for (int half = 0; half < 2; half++) {
                const int row = bm + wm * 32 + mi * 16 + (lane >> 2) + half * 8;
                float vx = acc[mi][ni][half * 2 + 0] + bv.x;
                float vy = acc[mi][ni][half * 2 + 1] + bv.y;
                if (MODE == 0) {
                    const int sec  = col >> 10;          // 0=q, 1=k, 2=v
                    const int cc   = col & 1023;
                    const int head = cc >> 6;
                    const int dpos = cc & 63;
                    const int b  = row >> 10;
                    const int tt = row & 1023;
                    const int bh2 = b * NH + head;
                    __nv_bfloat16 hx, lx, hy, ly;
                    bsplit(vx, hx, lx); bsplit(vy, hy, ly);
                    __nv_bfloat16* dh = (sec == 0) ? g_Qh : (sec == 1) ? g_Kh : g_Vh;
                    __nv_bfloat16* dl = (sec == 0) ? g_Qlo : (sec == 1) ? g_Klo : g_Vlo;
                    size_t o = ((size_t)bh2 * TSEQ + tt) * DH + dpos;
                    __nv_bfloat162 hv; hv.x = hx; hv.y = hy;
                    __nv_bfloat162 lv; lv.x = lx; lv.y = ly;
                    *(__nv_bfloat162*)(dh + o) = hv;
                    *(__nv_bfloat162*)(dl + o) = lv;
                } else {
                    float2 v2; v2.x = vx; v2.y = vy;
                    *(float2*)(out + (size_t)row * N + col) = v2;
                }
            }
        }
    }
}

// ---------------------------------------------------------------------------
// Tensor-core flash attention, 3xBF16, register-resident P, double-buffered
// K/V, trans-ldmatrix V. (unchanged from R13)
// ---------------------------------------------------------------------------
#define ABQ   128
#define ABK   64
#define SQH 0
#define SQL 16384
#define SKV 32768
#define ASMEM 98304

__device__ __forceinline__ void attn_load_kv(uint32_t sbuf,
        const __nv_bfloat16* Khp, const __nv_bfloat16* Klp,
        const __nv_bfloat16* Vhp, const __nv_bfloat16* Vlp,
        int k0, int tid)
{
#pragma unroll
    for (int l = 0; l < 4; l++) {
        int idx = tid + l * 256;
        int panel = idx >> 9;
        int rem = idx & 511;
        int r = rem >> 3, ch = rem & 7;
        uint32_t off = (uint32_t)r * 128 + ch * 16;
        uint32_t sw = off ^ ((off >> 3) & 0x70);
        cp_async16(sbuf + (panel ? 8192 : 0) + sw,
                   (panel ? Klp : Khp) + (size_t)(k0 + r) * DH + ch * 8);
        cp_async16(sbuf + (panel ? 24576 : 16384) + sw,
                   (panel ? Vlp : Vhp) + (size_t)(k0 + r) * DH + ch * 8);
    }
}

__global__ __launch_bounds__(256, 2) void attn_kernel()
{
    extern __shared__ char smc[];
    const uint32_t sb = smem_u32(smc);

    const int qi = gridDim.x - 1 - blockIdx.x;
    const int bh = blockIdx.y;
    const int bb = bh >> 4, hh = bh & 15;
    const __nv_bfloat16* Qhp = g_Qh  + (size_t)bh * TSEQ * DH;
    const __nv_bfloat16* Qlp = g_Qlo + (size_t)bh * TSEQ * DH;
    const __nv_bfloat16* Khp = g_Kh  + (size_t)bh * TSEQ * DH;
    const __nv_bfloat16* Klp = g_Klo + (size_t)bh * TSEQ * DH;
    const __nv_bfloat16* Vhp = g_Vh  + (size_t)bh * TSEQ * DH;
    const __nv_bfloat16* Vlp = g_Vlo + (size_t)bh * TSEQ * DH;

    const int tid  = threadIdx.x;
    const int warp = tid >> 5;
    const int lane = tid & 31;
    const int rA   = lane >> 2;
    const int qcol = (lane & 3) * 2;

    const int acb  = (lane >> 4) & 1;
    const int bcb  = (lane >> 3) & 1;
    const int brow = (lane & 7) + ((lane & 16) >> 1);
    const int koff = (((lane >> 3) & 1) << 3) + (lane & 7);
    const int noct = lane >> 4;

#pragma unroll
    for (int l = 0; l < 8; l++) {
        int idx = tid + l * 256;
        int panel = idx >> 10;
        int rem = idx & 1023;
        int r = rem >> 3, ch = rem & 7;
        uint32_t off = (uint32_t)r * 128 + ch * 16;
        uint32_t sw = off ^ ((off >> 3) & 0x70);
        const __nv_bfloat16* src = (panel ? Qlp : Qhp) + (size_t)(qi * ABQ + r) * DH + ch * 8;
        cp_async16(sb + (panel ? SQL : SQH) + sw, src);
    }
    attn_load_kv(sb + SKV, Khp, Klp, Vhp, Vlp, 0, tid);
    CP_COMMIT();

    float o[8][4];
#pragma unroll
    for (int ni = 0; ni < 8; ni++)
#pragma unroll
        for (int j = 0; j < 4; j++) o[ni][j] = 0.0f;
    float mA = -1e30f, mB = -1e30f, lAcc = 0.0f, lBcc = 0.0f;

    const float CS = 0.18033688011112042f;
    const int ntiles = 2 * qi + 2;

    for (int kt = 0; kt < ntiles; kt++) {
        if (kt + 1 < ntiles) {
            attn_load_kv(sb + SKV + ((kt + 1) & 1) * 32768,
                         Khp, Klp, Vhp, Vlp, (kt + 1) * ABK, tid);
            CP_COMMIT();
            asm volatile("cp.async.wait_group 1;" ::: "memory");
        } else {
            asm volatile("cp.async.wait_group 0;" ::: "memory");
        }
        __syncthreads();

        const uint32_t skv = sb + SKV + (uint32_t)(kt & 1) * 32768;

        if (kt * ABK <= qi * ABQ + warp * 16 + 15) {
            float s[8][4];
#pragma unroll
            for (int ni = 0; ni < 8; ni++)
#pragma unroll
                for (int j = 0; j < 4; j++) s[ni][j] = 0.0f;

            const int aQrow = warp * 16 + (lane & 15);
            const uint32_t a_ro = (uint32_t)aQrow * 128;
            const int a_rx = aQrow & 7;
#pragma unroll
            for (int ks = 0; ks < 4; ks++) {
                uint32_t ah[4], al[4], kh[4][4], kl[4][4];
                uint32_t ao = a_ro + (uint32_t)(((ks * 2 + acb) ^ a_rx) << 4);
                ldsm_x4(ah, sb + SQH + ao);
                ldsm_x4(al, sb + SQL + ao);
#pragma unroll
                for (int pi = 0; pi < 4; pi++) {
                    int br = pi * 16 + brow;
                    uint32_t bo = (uint32_t)br * 128 +
                                  (uint32_t)(((ks * 2 + bcb) ^ (br & 7)) << 4);
                    ldsm_x4(kh[pi], skv + bo);
                    ldsm_x4(kl[pi], skv + 8192 + bo);
                }
#pragma unroll
                for (int ni = 0; ni < 8; ni++) {
                    const int pi = ni >> 1, j0 = (ni & 1) * 2;
                    mma_bf16(s[ni], al, kh[pi][j0], kh[pi][j0 + 1]);
                    mma_bf16(s[ni], ah, kl[pi][j0], kl[pi][j0 + 1]);
                    mma_bf16(s[ni], ah, kh[pi][j0], kh[pi][j0 + 1]);
                }
            }

            const bool needmask = (kt * ABK + ABK - 1 > qi * ABQ + warp * 16);
            const int rowgA = qi * ABQ + warp * 16 + rA;
            const int rowgB = rowgA + 8;
            const int cb = kt * ABK + qcol;
#pragma unroll
            for (int ni = 0; ni < 8; ni++) {
                float z0 = s[ni][0] * CS, z1 = s[ni][1] * CS;
                float z2 = s[ni][2] * CS, z3 = s[ni][3] * CS;
                if (needmask) {
                    int c0 = cb + ni * 8, c1 = c0 + 1;
                    if (c0 > rowgA) z0 = -1e30f;
                    if (c1 > rowgA) z1 = -1e30f;
                    if (c0 > rowgB) z2 = -1e30f;
                    if (c1 > rowgB) z3 = -1e30f;
                }
                s[ni][0] = z0; s[ni][1] = z1; s[ni][2] = z2; s[ni][3] = z3;
            }

            float mtA = -1e30f, mtB = -1e30f;
#pragma unroll
            for (int ni = 0; ni < 8; ni++) {
                mtA = fmaxf(mtA, fmaxf(s[ni][0], s[ni][1]));
                mtB = fmaxf(mtB, fmaxf(s[ni][2], s[ni][3]));
            }
            mtA = fmaxf(mtA, __shfl_xor_sync(0xffffffffu, mtA, 1));
            mtA = fmaxf(mtA, __shfl_xor_sync(0xffffffffu, mtA, 2));
            mtB = fmaxf(mtB, __shfl_xor_sync(0xffffffffu, mtB, 1));
            mtB = fmaxf(mtB, __shfl_xor_sync(0xffffffffu, mtB, 2));

            const float mnA = fmaxf(mA, mtA);
            const float mnB = fmaxf(mB, mtB);
            const float aAl = fast_exp2(mA - mnA);
            const float aBl = fast_exp2(mB - mnB);
            mA = mnA; mB = mnB;

            float psA = 0.0f, psB = 0.0f;
#pragma unroll
            for (int ni = 0; ni < 8; ni++) {
                float p0 = fast_exp2(s[ni][0] - mnA);
                float p1 = fast_exp2(s[ni][1] - mnA);
                float p2 = fast_exp2(s[ni][2] - mnB);
                float p3 = fast_exp2(s[ni][3] - mnB);
                psA += p0 + p1; psB += p2 + p3;
                s[ni][0] = p0; s[ni][1] = p1; s[ni][2] = p2; s[ni][3] = p3;
            }
            psA += __shfl_xor_sync(0xffffffffu, psA, 1);
            psA += __shfl_xor_sync(0xffffffffu, psA, 2);
            psB += __shfl_xor_sync(0xffffffffu, psB, 1);
            psB += __shfl_xor_sync(0xffffffffu, psB, 2);
            lAcc = lAcc * aAl + psA;
            lBcc = lBcc * aBl + psB;

#pragma unroll
            for (int ni = 0; ni < 8; ni++) {
                o[ni][0] *= aAl; o[ni][1] *= aAl;
                o[ni][2] *= aBl; o[ni][3] *= aBl;
            }

#pragma unroll
            for (int j = 0; j < 4; j++) {
                uint32_t pa_h[4], pa_l[4];
#pragma unroll
                for (int half = 0; half < 2; half++) {
                    const float* sp = s[2 * j + half];
                    __nv_bfloat162 h0 = __floats2bfloat162_rn(sp[0], sp[1]);
                    __nv_bfloat162 h1 = __floats2bfloat162_rn(sp[2], sp[3]);
                    __nv_bfloat162 l0 = __floats2bfloat162_rn(
                        sp[0] - __bfloat162float(h0.x), sp[1] - __bfloat162float(h0.y));
                    __nv_bfloat162 l1 = __floats2bfloat162_rn(
                        sp[2] - __bfloat162float(h1.x), sp[3] - __bfloat162float(h1.y));
                    pa_h[half * 2 + 0] = *(uint32_t*)&h0;
                    pa_h[half * 2 + 1] = *(uint32_t*)&h1;
                    pa_l[half * 2 + 0] = *(uint32_t*)&l0;
                    pa_l[half * 2 + 1] = *(uint32_t*)&l1;
                }

                uint32_t vh[4][4], vl[4][4];
                const int vrow = j * 16 + koff;
                const uint32_t vro = (uint32_t)vrow * 128;
                const int v_rx = vrow & 7;
#pragma unroll
                for (int pi = 0; pi < 4; pi++) {
                    uint32_t chv = (uint32_t)(2 * pi + noct);
                    uint32_t bo = vro + ((chv ^ (uint32_t)v_rx) << 4);
                    ldsm_x4_trans(vh[pi], skv + 16384 + bo);
                    ldsm_x4_trans(vl[pi], skv + 24576 + bo);
                }
#pragma unroll
                for (int ni = 0; ni < 8; ni++) {
                    const int pi = ni >> 1, j0 = (ni & 1) * 2;
                    mma_bf16(o[ni], pa_l, vh[pi][j0], vh[pi][j0 + 1]);
                    mma_bf16(o[ni], pa_h, vl[pi][j0], vl[pi][j0 + 1]);
                    mma_bf16(o[ni], pa_h, vh[pi][j0], vh[pi][j0 + 1]);
                }
            }
        }
        __syncthreads();
    }

    const float invA = 1.0f / lAcc;
    const float invB = 1.0f / lBcc;
    const int tA = qi * ABQ + warp * 16 + rA;
    const int tB = tA + 8;
    const size_t baseA = ((size_t)bb * TSEQ + tA) * CDIM + hh * DH;
    const size_t baseB = ((size_t)bb * TSEQ + tB) * CDIM + hh * DH;
#pragma unroll
    for (int ni = 0; ni < 8; ni++) {
        int col = ni * 8 + qcol;
        float yA0 = o[ni][0] * invA, yA1 = o[ni][1] * invA;
        float yB0 = o[ni][2] * invB, yB1 = o[ni][3] * invB;
        __nv_bfloat16 h0, l0, h1, l1;
        __nv_bfloat162 hv, lv;
        bsplit(yA0, h0, l0); bsplit(yA1, h1, l1);
        hv.x = h0; hv.y = h1; lv.x = l0; lv.y = l1;
        *(__nv_bfloat162*)(g_Yhi + baseA + col) = hv;
        *(__nv_bfloat162*)(g_Ylo + baseA + col) = lv;
        bsplit(yB0, h0, l0); bsplit(yB1, h1, l1);
        hv.x = h0; hv.y = h1; lv.x = l0; lv.y = l1;
        *(__nv_bfloat162*)(g_Yhi + baseB + col) = hv;
        *(__nv_bfloat162*)(g_Ylo + baseB + col) = lv;
    }
}

// ---------------------------------------------------------------------------
// Launch
// ---------------------------------------------------------------------------
extern "C" void kernel_launch(void* const* d_in, const int* in_sizes, int n_in,
                              void* d_out, int out_size)
{
    const float* x      = (const float*)d_in[0];
    const float* w_attn = (const float*)d_in[1];
    const float* b_attn = (const float*)d_in[2];
    const float* w_proj = (const float*)d_in[3];
    const float* b_proj = (const float*)d_in[4];
    float* out = (float*)d_out;

    // 0) Fused preprocessing (pure splits, no transpose)
    {
        preproc_kernel<<<8192, 256>>>(x, w_attn, w_proj);
    }

    // 1) QKV GEMM (3xbf16, trans-B, BN=64, 3 CTAs/SM)
    {
        cudaFuncSetAttribute(tc_gemm<3 * CDIM, 0>,
                             cudaFuncAttributeMaxDynamicSharedMemorySize, GSMEM);
        dim3 grid(3 * CDIM / GBN, MROWS / GBM);   // (48, 32)
        tc_gemm<3 * CDIM, 0><<<grid, 256, GSMEM>>>(b_attn, nullptr);
    }

    // 2) Tensor-core flash attention (3xbf16, trans-ldmatrix V)
    {
        cudaFuncSetAttribute(attn_kernel,
                             cudaFuncAttributeMaxDynamicSharedMemorySize, ASMEM);
        dim3 grid(TSEQ / ABQ, NB * NH);           // (8, 64)
        attn_kernel<<<grid, 256, ASMEM>>>();
    }

    // 3) Output projection (3xbf16, trans-B, BN=64, 3 CTAs/SM)
    {
        cudaFuncSetAttribute(tc_gemm<CDIM, 1>,
                             cudaFuncAttributeMaxDynamicSharedMemorySize, GSMEM);
        dim3 grid(CDIM / GBN, MROWS / GBM);       // (16, 32)
        tc_gemm<CDIM, 1><<<grid, 256, GSMEM>>>(b_proj, out);
    }
}